// round 1
// baseline (speedup 1.0000x reference)
#include <cuda_runtime.h>
#include <math.h>

// Problem: B=4, S=4096, H=1024, D=64
#define BATCH 4
#define SEQ   4096
#define HID   1024
#define DIM   64
#define M_TOT (BATCH*SEQ)   // 16384

// Scratch for projected q, k, v  (each 16384 x 64 fp32 = 4 MiB)
__device__ float g_q[M_TOT * DIM];
__device__ float g_k[M_TOT * DIM];
__device__ float g_v[M_TOT * DIM];

// ---------------------------------------------------------------------------
// Projection GEMM: Y[M,64] = X[M,1024] @ W[1024,64] + b
// BM=128, BN=64, BK=16, 256 threads, each thread computes 8x4 outputs.
// blockIdx.z selects which projection (q/k/v).
// ---------------------------------------------------------------------------
__global__ __launch_bounds__(256) void proj_kernel(
    const float* __restrict__ Xq, const float* __restrict__ Xk, const float* __restrict__ Xv,
    const float* __restrict__ Wq, const float* __restrict__ bq,
    const float* __restrict__ Wk, const float* __restrict__ bk,
    const float* __restrict__ Wv, const float* __restrict__ bv)
{
    const float* X; const float* W; const float* bias; float* Y;
    if (blockIdx.z == 0)      { X = Xq; W = Wq; bias = bq; Y = g_q; }
    else if (blockIdx.z == 1) { X = Xk; W = Wk; bias = bk; Y = g_k; }
    else                      { X = Xv; W = Wv; bias = bv; Y = g_v; }

    __shared__ float As[16][129];  // [k][m], padded vs bank conflicts
    __shared__ float Bs[16][64];   // [k][n]

    const int tid = threadIdx.x;
    const int tx  = tid & 15;   // 0..15 (column group, 4 cols each)
    const int ty  = tid >> 4;   // 0..15 (row group, 8 rows each)
    const int row0 = blockIdx.x * 128;

    float acc[8][4];
    #pragma unroll
    for (int i = 0; i < 8; i++)
        #pragma unroll
        for (int j = 0; j < 4; j++) acc[i][j] = 0.f;

    for (int k0 = 0; k0 < HID; k0 += 16) {
        // Load A tile 128x16 -> As[k][m]
        {
            const int kk = tid & 15;
            #pragma unroll
            for (int it = 0; it < 8; it++) {
                const int m = (tid >> 4) + it * 16;
                As[kk][m] = X[(size_t)(row0 + m) * HID + k0 + kk];
            }
        }
        // Load B tile 16x64 -> Bs[k][n]
        {
            const int n = tid & 63;
            #pragma unroll
            for (int it = 0; it < 4; it++) {
                const int kk = (tid >> 6) + it * 4;
                Bs[kk][n] = W[(size_t)(k0 + kk) * DIM + n];
            }
        }
        __syncthreads();

        #pragma unroll
        for (int kk = 0; kk < 16; kk++) {
            float a[8], b[4];
            #pragma unroll
            for (int i = 0; i < 8; i++) a[i] = As[kk][ty * 8 + i];
            #pragma unroll
            for (int j = 0; j < 4; j++) b[j] = Bs[kk][tx * 4 + j];
            #pragma unroll
            for (int i = 0; i < 8; i++)
                #pragma unroll
                for (int j = 0; j < 4; j++)
                    acc[i][j] = fmaf(a[i], b[j], acc[i][j]);
        }
        __syncthreads();
    }

    #pragma unroll
    for (int j = 0; j < 4; j++) {
        const float bb = bias[tx * 4 + j];
        #pragma unroll
        for (int i = 0; i < 8; i++) {
            Y[(size_t)(row0 + ty * 8 + i) * DIM + tx * 4 + j] = acc[i][j] + bb;
        }
    }
}

// ---------------------------------------------------------------------------
// Flash attention (fp32). One block = one 64-row Q tile of one batch.
// 256 threads = 16x16 grid, 4x4 microtiles. Online softmax over 64 key tiles.
// ---------------------------------------------------------------------------
#define QS 65   // stride for Qt/Kt/Ss (padded)
#define VS 68   // stride for Vs (padded, 16B-aligned rows for float4 stores)
#define ATTN_SMEM_FLOATS (3*64*QS + 64*VS + 64*3 + 64)
#define ATTN_SMEM_BYTES  (ATTN_SMEM_FLOATS * 4)

__global__ __launch_bounds__(256) void attn_kernel(
    const int* __restrict__ mask, float* __restrict__ out)
{
    extern __shared__ float sm[];
    float* Qt        = sm;                       // [64][QS]  d-major: Qt[d*QS + r]
    float* Kt        = Qt + 64 * QS;             // [64][QS]  d-major: Kt[d*QS + c]
    float* Ss        = Kt + 64 * QS;             // [64][QS]  row-major scores / probs
    float* Vs        = Ss + 64 * QS;             // [64][VS]  key-major: Vs[key*VS + d]
    float* row_m     = Vs + 64 * VS;             // [64]
    float* row_l     = row_m + 64;               // [64]
    float* row_scale = row_l + 64;               // [64]
    float* kmaskf    = row_scale + 64;           // [64]

    const int tid = threadIdx.x;
    const int tx  = tid & 15;
    const int ty  = tid >> 4;
    const int r0  = ty * 4;
    const int c0  = tx * 4;

    const int b  = blockIdx.y;
    const int q0 = blockIdx.x * 64;
    const float* qbase = g_q + (size_t)b * SEQ * DIM;
    const float* kbase = g_k + (size_t)b * SEQ * DIM;
    const float* vbase = g_v + (size_t)b * SEQ * DIM;
    const int*   mbase = mask + (size_t)b * SEQ;

    // Load Q tile transposed, pre-scaled by 1/sqrt(D) = 0.125
    {
        const int r  = tid >> 2;
        const int d0 = (tid & 3) * 16;
        const float4* src = (const float4*)(qbase + (size_t)(q0 + r) * DIM + d0);
        #pragma unroll
        for (int i4 = 0; i4 < 4; i4++) {
            float4 v = src[i4];
            Qt[(d0 + i4*4 + 0) * QS + r] = v.x * 0.125f;
            Qt[(d0 + i4*4 + 1) * QS + r] = v.y * 0.125f;
            Qt[(d0 + i4*4 + 2) * QS + r] = v.z * 0.125f;
            Qt[(d0 + i4*4 + 3) * QS + r] = v.w * 0.125f;
        }
    }
    if (tid < 64) { row_m[tid] = -1e30f; row_l[tid] = 0.f; }

    float acc[4][4];
    #pragma unroll
    for (int i = 0; i < 4; i++)
        #pragma unroll
        for (int j = 0; j < 4; j++) acc[i][j] = 0.f;

    for (int kt = 0; kt < SEQ / 64; kt++) {
        const int k0 = kt * 64;
        // ---- load K tile (transposed), V tile (row-major), mask tile ----
        {
            const int r  = tid >> 2;
            const int d0 = (tid & 3) * 16;
            const float4* ksrc = (const float4*)(kbase + (size_t)(k0 + r) * DIM + d0);
            #pragma unroll
            for (int i4 = 0; i4 < 4; i4++) {
                float4 v = ksrc[i4];
                Kt[(d0 + i4*4 + 0) * QS + r] = v.x;
                Kt[(d0 + i4*4 + 1) * QS + r] = v.y;
                Kt[(d0 + i4*4 + 2) * QS + r] = v.z;
                Kt[(d0 + i4*4 + 3) * QS + r] = v.w;
            }
            const float4* vsrc = (const float4*)(vbase + (size_t)(k0 + r) * DIM + d0);
            float4* vdst = (float4*)(Vs + r * VS + d0);
            #pragma unroll
            for (int i4 = 0; i4 < 4; i4++) vdst[i4] = vsrc[i4];
        }
        if (tid < 64) kmaskf[tid] = (mbase[k0 + tid] != 0) ? 1.f : 0.f;
        __syncthreads();

        // ---- S = Q @ K^T (scaled), masked, into smem ----
        {
            float sacc[4][4];
            #pragma unroll
            for (int i = 0; i < 4; i++)
                #pragma unroll
                for (int j = 0; j < 4; j++) sacc[i][j] = 0.f;

            #pragma unroll 8
            for (int d = 0; d < DIM; d++) {
                float a[4], bb[4];
                #pragma unroll
                for (int i = 0; i < 4; i++) a[i]  = Qt[d * QS + r0 + i];
                #pragma unroll
                for (int j = 0; j < 4; j++) bb[j] = Kt[d * QS + c0 + j];
                #pragma unroll
                for (int i = 0; i < 4; i++)
                    #pragma unroll
                    for (int j = 0; j < 4; j++)
                        sacc[i][j] = fmaf(a[i], bb[j], sacc[i][j]);
            }
            #pragma unroll
            for (int j = 0; j < 4; j++) {
                const bool keep = (kmaskf[c0 + j] != 0.f);
                #pragma unroll
                for (int i = 0; i < 4; i++)
                    Ss[(r0 + i) * QS + c0 + j] = keep ? sacc[i][j] : -1e9f;
            }
        }
        __syncthreads();

        // ---- online softmax over this 64-key tile ----
        {
            const int row = tid >> 2;          // 0..63
            const int cs  = (tid & 3) * 16;    // 4 threads per row
            float* srow = Ss + row * QS + cs;
            float mx = -1e30f;
            #pragma unroll
            for (int i = 0; i < 16; i++) mx = fmaxf(mx, srow[i]);
            mx = fmaxf(mx, __shfl_xor_sync(0xffffffffu, mx, 1));
            mx = fmaxf(mx, __shfl_xor_sync(0xffffffffu, mx, 2));

            const float m_old = row_m[row];
            const float m_new = fmaxf(m_old, mx);

            float sum = 0.f;
            #pragma unroll
            for (int i = 0; i < 16; i++) {
                float p = __expf(srow[i] - m_new);
                srow[i] = p;
                sum += p;
            }
            sum += __shfl_xor_sync(0xffffffffu, sum, 1);
            sum += __shfl_xor_sync(0xffffffffu, sum, 2);

            if ((tid & 3) == 0) {
                const float corr = __expf(m_old - m_new);
                row_scale[row] = corr;
                row_l[row]     = row_l[row] * corr + sum;
                row_m[row]     = m_new;
            }
        }
        __syncthreads();

        // ---- acc = acc * corr + P @ V ----
        {
            float corr[4];
            #pragma unroll
            for (int i = 0; i < 4; i++) corr[i] = row_scale[r0 + i];
            #pragma unroll
            for (int i = 0; i < 4; i++)
                #pragma unroll
                for (int j = 0; j < 4; j++) acc[i][j] *= corr[i];

            #pragma unroll 8
            for (int key = 0; key < 64; key++) {
                float p[4], v[4];
                #pragma unroll
                for (int i = 0; i < 4; i++) p[i] = Ss[(r0 + i) * QS + key];
                #pragma unroll
                for (int j = 0; j < 4; j++) v[j] = Vs[key * VS + c0 + j];
                #pragma unroll
                for (int i = 0; i < 4; i++)
                    #pragma unroll
                    for (int j = 0; j < 4; j++)
                        acc[i][j] = fmaf(p[i], v[j], acc[i][j]);
            }
        }
        __syncthreads();
    }

    // ---- epilogue: normalize and store ----
    #pragma unroll
    for (int i = 0; i < 4; i++) {
        const float inv_l = 1.f / row_l[r0 + i];
        float* orow = out + (size_t)(b * SEQ + q0 + r0 + i) * DIM + c0;
        #pragma unroll
        for (int j = 0; j < 4; j++) orow[j] = acc[i][j] * inv_l;
    }
}

// ---------------------------------------------------------------------------
extern "C" void kernel_launch(void* const* d_in, const int* in_sizes, int n_in,
                              void* d_out, int out_size)
{
    const float* query = (const float*)d_in[0];
    const float* key_  = (const float*)d_in[1];
    const float* value = (const float*)d_in[2];
    const int*   mask  = (const int*)d_in[3];
    const float* Wq = (const float*)d_in[4];
    const float* bq = (const float*)d_in[5];
    const float* Wk = (const float*)d_in[6];
    const float* bk = (const float*)d_in[7];
    const float* Wv = (const float*)d_in[8];
    const float* bv = (const float*)d_in[9];
    float* out = (float*)d_out;

    // Projections: q = query@Wq+bq, k = key@Wk+bk, v = value@Wv+bv
    dim3 gp(M_TOT / 128, 1, 3);
    proj_kernel<<<gp, 256>>>(query, key_, value, Wq, bq, Wk, bk, Wv, bv);

    // Attention (needs >48KB dynamic smem)
    cudaFuncSetAttribute(attn_kernel, cudaFuncAttributeMaxDynamicSharedMemorySize,
                         ATTN_SMEM_BYTES);
    dim3 ga(SEQ / 64, BATCH);
    attn_kernel<<<ga, 256, ATTN_SMEM_BYTES>>>(mask, out);
}

// round 2
// speedup vs baseline: 2.9065x; 2.9065x over previous
#include <cuda_runtime.h>
#include <stdint.h>

// Problem: B=4, S=4096, H=1024, D=64
#define BATCH 4
#define SEQ   4096
#define HID   1024
#define DIM   64
#define M_TOT (BATCH*SEQ)   // 16384

// Scratch for projected q, k, v
__device__ float g_q[M_TOT * DIM];
__device__ float g_k[M_TOT * DIM];
__device__ float g_v[M_TOT * DIM];

// ---------------------------------------------------------------------------
// tf32 helpers + mma.m16n8k8 wrapper
// ---------------------------------------------------------------------------
__device__ __forceinline__ uint32_t f2tf_u(float x) {
    uint32_t u;
    asm("cvt.rna.tf32.f32 %0, %1;" : "=r"(u) : "f"(x));
    return u;
}
__device__ __forceinline__ float tfv(float x) { return __uint_as_float(f2tf_u(x)); }

__device__ __forceinline__ void mma8(float* c,
                                     uint32_t a0, uint32_t a1, uint32_t a2, uint32_t a3,
                                     uint32_t b0, uint32_t b1) {
    asm volatile(
        "mma.sync.aligned.m16n8k8.row.col.f32.tf32.tf32.f32 "
        "{%0,%1,%2,%3},{%4,%5,%6,%7},{%8,%9},{%0,%1,%2,%3};"
        : "+f"(c[0]), "+f"(c[1]), "+f"(c[2]), "+f"(c[3])
        : "r"(a0), "r"(a1), "r"(a2), "r"(a3), "r"(b0), "r"(b1));
}

// ---------------------------------------------------------------------------
// Projection GEMM (tf32 mma): Y[M,64] = X[M,1024] @ W[1024,64] + b
// 256 threads = 8 warps; block M-tile 128; warp = 16 rows x 64 cols (8 n-tiles).
// K staged in double-buffered chunks of 32. One barrier per K-step.
// ---------------------------------------------------------------------------
#define XS_STR 36
#define WS_STR 72
#define P_SM_X0 0
#define P_SM_X1 (128*XS_STR)
#define P_SM_W0 (2*128*XS_STR)
#define P_SM_W1 (P_SM_W0 + 32*WS_STR)
#define PROJ_SMEM_FL (P_SM_W1 + 32*WS_STR)
#define PROJ_SMEM_BYTES (PROJ_SMEM_FL * 4)

__global__ __launch_bounds__(256) void proj_mma(
    const float* __restrict__ Xq, const float* __restrict__ Xk, const float* __restrict__ Xv,
    const float* __restrict__ Wq, const float* __restrict__ bq,
    const float* __restrict__ Wk, const float* __restrict__ bk,
    const float* __restrict__ Wv, const float* __restrict__ bv)
{
    const float* X; const float* W; const float* bias; float* Y;
    if (blockIdx.z == 0)      { X = Xq; W = Wq; bias = bq; Y = g_q; }
    else if (blockIdx.z == 1) { X = Xk; W = Wk; bias = bk; Y = g_k; }
    else                      { X = Xv; W = Wv; bias = bv; Y = g_v; }

    extern __shared__ float sm[];
    const int tid  = threadIdx.x;
    const int warp = tid >> 5, lane = tid & 31;
    const int g = lane >> 2, t = lane & 3;
    const int wrow = warp * 16;
    const int row0 = blockIdx.x * 128;

    // prefetch mapping
    const int xr_ = tid >> 3;          // 0..31
    const int xc4 = (tid & 7) * 4;     // 0..28
    const int wr_ = tid >> 4;          // 0..15
    const int wc4 = (tid & 15) * 4;    // 0..60

    float4 xg[4], wg[2];

    // fetch step 0
    #pragma unroll
    for (int i = 0; i < 4; i++)
        xg[i] = *(const float4*)(X + (size_t)(row0 + xr_ + 32*i) * HID + 0 + xc4);
    #pragma unroll
    for (int i = 0; i < 2; i++)
        wg[i] = *(const float4*)(W + (size_t)(0 + wr_ + 16*i) * DIM + wc4);

    // store step 0 into buf 0
    {
        float* xd = sm + P_SM_X0;
        float* wd = sm + P_SM_W0;
        #pragma unroll
        for (int i = 0; i < 4; i++)
            *(float4*)(xd + (xr_ + 32*i)*XS_STR + xc4) =
                make_float4(tfv(xg[i].x), tfv(xg[i].y), tfv(xg[i].z), tfv(xg[i].w));
        #pragma unroll
        for (int i = 0; i < 2; i++)
            *(float4*)(wd + (wr_ + 16*i)*WS_STR + wc4) =
                make_float4(tfv(wg[i].x), tfv(wg[i].y), tfv(wg[i].z), tfv(wg[i].w));
    }
    __syncthreads();

    float c[8][4];
    #pragma unroll
    for (int nt = 0; nt < 8; nt++)
        #pragma unroll
        for (int j = 0; j < 4; j++) c[nt][j] = 0.f;

    for (int s = 0; s < 32; s++) {
        const int cur = s & 1;
        if (s < 31) {
            const int k0 = (s + 1) * 32;
            #pragma unroll
            for (int i = 0; i < 4; i++)
                xg[i] = *(const float4*)(X + (size_t)(row0 + xr_ + 32*i) * HID + k0 + xc4);
            #pragma unroll
            for (int i = 0; i < 2; i++)
                wg[i] = *(const float4*)(W + (size_t)(k0 + wr_ + 16*i) * DIM + wc4);
        }
        const float* Xc = sm + (cur ? P_SM_X1 : P_SM_X0);
        const float* Wc = sm + (cur ? P_SM_W1 : P_SM_W0);
        const float* xa = Xc + (wrow + g) * XS_STR + t;
        const float* wb = Wc + t * WS_STR + g;

        #pragma unroll
        for (int kc = 0; kc < 4; kc++) {
            uint32_t a0 = __float_as_uint(xa[kc*8]);
            uint32_t a1 = __float_as_uint(xa[kc*8 + 8*XS_STR]);
            uint32_t a2 = __float_as_uint(xa[kc*8 + 4]);
            uint32_t a3 = __float_as_uint(xa[kc*8 + 4 + 8*XS_STR]);
            #pragma unroll
            for (int nt = 0; nt < 8; nt++) {
                uint32_t b0 = __float_as_uint(wb[(kc*8)    *WS_STR + nt*8]);
                uint32_t b1 = __float_as_uint(wb[(kc*8 + 4)*WS_STR + nt*8]);
                mma8(c[nt], a0, a1, a2, a3, b0, b1);
            }
        }
        if (s < 31) {
            float* xd = sm + (cur ? P_SM_X0 : P_SM_X1);
            float* wd = sm + (cur ? P_SM_W0 : P_SM_W1);
            #pragma unroll
            for (int i = 0; i < 4; i++)
                *(float4*)(xd + (xr_ + 32*i)*XS_STR + xc4) =
                    make_float4(tfv(xg[i].x), tfv(xg[i].y), tfv(xg[i].z), tfv(xg[i].w));
            #pragma unroll
            for (int i = 0; i < 2; i++)
                *(float4*)(wd + (wr_ + 16*i)*WS_STR + wc4) =
                    make_float4(tfv(wg[i].x), tfv(wg[i].y), tfv(wg[i].z), tfv(wg[i].w));
        }
        __syncthreads();
    }

    // epilogue: add bias, store
    float* yb = Y + (size_t)(row0 + wrow + g) * DIM + 2*t;
    #pragma unroll
    for (int nt = 0; nt < 8; nt++) {
        float2 bv = *(const float2*)(bias + nt*8 + 2*t);
        *(float2*)(yb + nt*8)          = make_float2(c[nt][0] + bv.x, c[nt][1] + bv.y);
        *(float2*)(yb + nt*8 + 8*DIM)  = make_float2(c[nt][2] + bv.x, c[nt][3] + bv.y);
    }
}

// ---------------------------------------------------------------------------
// Flash attention (tf32 mma). Block = 128 Q-rows of one batch; 8 warps; each
// warp owns 16 full rows (all 64 key cols / all 64 D cols) -> softmax stats
// fully in registers (quad shuffles). Double-buffered K/V tiles (64 keys),
// register prefetch, ONE __syncthreads per key tile.
// ---------------------------------------------------------------------------
#define QS_STR 68
#define KS_STR 68
#define VS_STR 72
#define SM_QS   0
#define SM_PS   (128*QS_STR)
#define SM_KS0  (SM_PS  + 128*QS_STR)
#define SM_KS1  (SM_KS0 + 64*KS_STR)
#define SM_VS0  (SM_KS1 + 64*KS_STR)
#define SM_VS1  (SM_VS0 + 64*VS_STR)
#define SM_MF0  (SM_VS1 + 64*VS_STR)
#define SM_MF1  (SM_MF0 + 64)
#define ATTN_SMEM_FL (SM_MF1 + 64)
#define ATTN_SMEM_BYTES (ATTN_SMEM_FL * 4)

__global__ __launch_bounds__(256) void attn_mma(
    const int* __restrict__ mask, float* __restrict__ out)
{
    extern __shared__ float sm[];
    const int tid  = threadIdx.x;
    const int warp = tid >> 5, lane = tid & 31;
    const int g = lane >> 2, t = lane & 3;
    const int wrow = warp * 16;

    const int b  = blockIdx.y;
    const int q0 = blockIdx.x * 128;
    const float* qb = g_q + ((size_t)b * SEQ + q0) * DIM;
    const float* kb = g_k + (size_t)b * SEQ * DIM;
    const float* vb = g_v + (size_t)b * SEQ * DIM;
    const int*   mb = mask + (size_t)b * SEQ;

    // ---- load Q tile (scaled by 1/8, tf32) ----
    {
        const int r = tid >> 1, d0 = (tid & 1) * 32;
        const float4* src = (const float4*)(qb + (size_t)r * DIM + d0);
        float* dst = sm + SM_QS + r * QS_STR + d0;
        #pragma unroll
        for (int i = 0; i < 8; i++) {
            float4 v = src[i];
            *(float4*)(dst + i*4) = make_float4(tfv(v.x*0.125f), tfv(v.y*0.125f),
                                                tfv(v.z*0.125f), tfv(v.w*0.125f));
        }
    }

    // ---- prefetch tile 0 ----
    const int pkey = tid >> 2;          // 0..63
    const int pd0  = (tid & 3) * 16;    // 0,16,32,48
    float4 kx[4], vx[4];
    int mreg = 0;
    {
        const float4* ks = (const float4*)(kb + (size_t)pkey * DIM + pd0);
        const float4* vs = (const float4*)(vb + (size_t)pkey * DIM + pd0);
        #pragma unroll
        for (int i = 0; i < 4; i++) { kx[i] = ks[i]; vx[i] = vs[i]; }
        if (tid < 64) mreg = mb[tid];
    }
    // store tile 0 into buf 0
    {
        float* kd = sm + SM_KS0 + pkey * KS_STR + pd0;
        float* vd = sm + SM_VS0 + pkey * VS_STR + pd0;
        #pragma unroll
        for (int i = 0; i < 4; i++) {
            *(float4*)(kd + i*4) = make_float4(tfv(kx[i].x), tfv(kx[i].y), tfv(kx[i].z), tfv(kx[i].w));
            *(float4*)(vd + i*4) = make_float4(tfv(vx[i].x), tfv(vx[i].y), tfv(vx[i].z), tfv(vx[i].w));
        }
        if (tid < 64) sm[SM_MF0 + tid] = (mreg != 0) ? 1.f : 0.f;
    }
    __syncthreads();

    float o[8][4];
    #pragma unroll
    for (int nt = 0; nt < 8; nt++)
        #pragma unroll
        for (int j = 0; j < 4; j++) o[nt][j] = 0.f;
    float m0 = -1e30f, m1 = -1e30f, l0 = 0.f, l1 = 0.f;

    const float* qa = sm + SM_QS + (wrow + g) * QS_STR + t;
    const float* pa = sm + SM_PS + (wrow + g) * QS_STR + t;
    float*       pw = sm + SM_PS + (wrow + g) * QS_STR + 2*t;

    for (int kt = 0; kt < 64; kt++) {
        const int cur = kt & 1;
        // prefetch next tile
        if (kt < 63) {
            const float4* ks = (const float4*)(kb + (size_t)((kt+1)*64 + pkey) * DIM + pd0);
            const float4* vs = (const float4*)(vb + (size_t)((kt+1)*64 + pkey) * DIM + pd0);
            #pragma unroll
            for (int i = 0; i < 4; i++) { kx[i] = ks[i]; vx[i] = vs[i]; }
            if (tid < 64) mreg = mb[(kt+1)*64 + tid];
        }
        const float* Kc = sm + (cur ? SM_KS1 : SM_KS0);
        const float* Vc = sm + (cur ? SM_VS1 : SM_VS0);
        const float* Mc = sm + (cur ? SM_MF1 : SM_MF0);

        // ---- S = Q @ K^T ----
        float c[8][4];
        #pragma unroll
        for (int nt = 0; nt < 8; nt++)
            #pragma unroll
            for (int j = 0; j < 4; j++) c[nt][j] = 0.f;

        const float* kbp = Kc + g * KS_STR + t;
        #pragma unroll
        for (int kc = 0; kc < 8; kc++) {
            uint32_t a0 = __float_as_uint(qa[kc*8]);
            uint32_t a1 = __float_as_uint(qa[kc*8 + 8*QS_STR]);
            uint32_t a2 = __float_as_uint(qa[kc*8 + 4]);
            uint32_t a3 = __float_as_uint(qa[kc*8 + 4 + 8*QS_STR]);
            #pragma unroll
            for (int nt = 0; nt < 8; nt++) {
                uint32_t b0 = __float_as_uint(kbp[nt*8*KS_STR + kc*8]);
                uint32_t b1 = __float_as_uint(kbp[nt*8*KS_STR + kc*8 + 4]);
                mma8(c[nt], a0, a1, a2, a3, b0, b1);
            }
        }

        // ---- mask + row max ----
        float mx0 = -1e30f, mx1 = -1e30f;
        #pragma unroll
        for (int nt = 0; nt < 8; nt++) {
            float2 mv = *(const float2*)(Mc + nt*8 + 2*t);
            if (mv.x == 0.f) { c[nt][0] = -1e9f; c[nt][2] = -1e9f; }
            if (mv.y == 0.f) { c[nt][1] = -1e9f; c[nt][3] = -1e9f; }
            mx0 = fmaxf(mx0, fmaxf(c[nt][0], c[nt][1]));
            mx1 = fmaxf(mx1, fmaxf(c[nt][2], c[nt][3]));
        }
        mx0 = fmaxf(mx0, __shfl_xor_sync(0xffffffffu, mx0, 1));
        mx0 = fmaxf(mx0, __shfl_xor_sync(0xffffffffu, mx0, 2));
        mx1 = fmaxf(mx1, __shfl_xor_sync(0xffffffffu, mx1, 1));
        mx1 = fmaxf(mx1, __shfl_xor_sync(0xffffffffu, mx1, 2));

        const float mn0 = fmaxf(m0, mx0), mn1 = fmaxf(m1, mx1);

        // ---- exp + row sums ----
        float s0 = 0.f, s1 = 0.f;
        #pragma unroll
        for (int nt = 0; nt < 8; nt++) {
            c[nt][0] = __expf(c[nt][0] - mn0);
            c[nt][1] = __expf(c[nt][1] - mn0);
            c[nt][2] = __expf(c[nt][2] - mn1);
            c[nt][3] = __expf(c[nt][3] - mn1);
            s0 += c[nt][0] + c[nt][1];
            s1 += c[nt][2] + c[nt][3];
        }
        s0 += __shfl_xor_sync(0xffffffffu, s0, 1);
        s0 += __shfl_xor_sync(0xffffffffu, s0, 2);
        s1 += __shfl_xor_sync(0xffffffffu, s1, 1);
        s1 += __shfl_xor_sync(0xffffffffu, s1, 2);

        const float co0 = __expf(m0 - mn0), co1 = __expf(m1 - mn1);
        m0 = mn0; m1 = mn1;
        l0 = l0 * co0 + s0;
        l1 = l1 * co1 + s1;

        // ---- write P (tf32), rescale O ----
        #pragma unroll
        for (int nt = 0; nt < 8; nt++) {
            *(float2*)(pw + nt*8)            = make_float2(tfv(c[nt][0]), tfv(c[nt][1]));
            *(float2*)(pw + nt*8 + 8*QS_STR) = make_float2(tfv(c[nt][2]), tfv(c[nt][3]));
            o[nt][0] *= co0; o[nt][1] *= co0;
            o[nt][2] *= co1; o[nt][3] *= co1;
        }
        __syncwarp();

        // ---- O += P @ V ----
        const float* vbp = Vc + t * VS_STR + g;
        #pragma unroll
        for (int kc = 0; kc < 8; kc++) {
            uint32_t a0 = __float_as_uint(pa[kc*8]);
            uint32_t a1 = __float_as_uint(pa[kc*8 + 8*QS_STR]);
            uint32_t a2 = __float_as_uint(pa[kc*8 + 4]);
            uint32_t a3 = __float_as_uint(pa[kc*8 + 4 + 8*QS_STR]);
            #pragma unroll
            for (int nt = 0; nt < 8; nt++) {
                uint32_t b0 = __float_as_uint(vbp[(kc*8)    *VS_STR + nt*8]);
                uint32_t b1 = __float_as_uint(vbp[(kc*8 + 4)*VS_STR + nt*8]);
                mma8(o[nt], a0, a1, a2, a3, b0, b1);
            }
        }

        // ---- stage next tile into the other buffer ----
        if (kt < 63) {
            float* kd = sm + (cur ? SM_KS0 : SM_KS1) + pkey * KS_STR + pd0;
            float* vd = sm + (cur ? SM_VS0 : SM_VS1) + pkey * VS_STR + pd0;
            #pragma unroll
            for (int i = 0; i < 4; i++) {
                *(float4*)(kd + i*4) = make_float4(tfv(kx[i].x), tfv(kx[i].y), tfv(kx[i].z), tfv(kx[i].w));
                *(float4*)(vd + i*4) = make_float4(tfv(vx[i].x), tfv(vx[i].y), tfv(vx[i].z), tfv(vx[i].w));
            }
            if (tid < 64) sm[(cur ? SM_MF0 : SM_MF1) + tid] = (mreg != 0) ? 1.f : 0.f;
        }
        __syncthreads();
    }

    // ---- epilogue: normalize + store ----
    const float i0 = 1.f / l0, i1 = 1.f / l1;
    float* ob = out + ((size_t)b * SEQ + q0 + wrow + g) * DIM + 2*t;
    #pragma unroll
    for (int nt = 0; nt < 8; nt++) {
        *(float2*)(ob + nt*8)          = make_float2(o[nt][0]*i0, o[nt][1]*i0);
        *(float2*)(ob + nt*8 + 8*DIM)  = make_float2(o[nt][2]*i1, o[nt][3]*i1);
    }
}

// ---------------------------------------------------------------------------
extern "C" void kernel_launch(void* const* d_in, const int* in_sizes, int n_in,
                              void* d_out, int out_size)
{
    const float* query = (const float*)d_in[0];
    const float* key_  = (const float*)d_in[1];
    const float* value = (const float*)d_in[2];
    const int*   mask  = (const int*)d_in[3];
    const float* Wq = (const float*)d_in[4];
    const float* bq = (const float*)d_in[5];
    const float* Wk = (const float*)d_in[6];
    const float* bk = (const float*)d_in[7];
    const float* Wv = (const float*)d_in[8];
    const float* bv = (const float*)d_in[9];
    float* out = (float*)d_out;

    cudaFuncSetAttribute(proj_mma, cudaFuncAttributeMaxDynamicSharedMemorySize,
                         PROJ_SMEM_BYTES);
    cudaFuncSetAttribute(attn_mma, cudaFuncAttributeMaxDynamicSharedMemorySize,
                         ATTN_SMEM_BYTES);

    dim3 gp(M_TOT / 128, 1, 3);
    proj_mma<<<gp, 256, PROJ_SMEM_BYTES>>>(query, key_, value,
                                           Wq, bq, Wk, bk, Wv, bv);

    dim3 ga(SEQ / 128, BATCH);
    attn_mma<<<ga, 256, ATTN_SMEM_BYTES>>>(mask, out);
}

// round 3
// speedup vs baseline: 3.1897x; 1.0974x over previous
#include <cuda_runtime.h>
#include <stdint.h>

// Problem: B=4, S=4096, H=1024, D=64
#define BATCH 4
#define SEQ   4096
#define HID   1024
#define DIM   64
#define M_TOT (BATCH*SEQ)   // 16384

// Scratch for projected q (pre-scaled by 1/8), k, v
__device__ float g_q[M_TOT * DIM];
__device__ float g_k[M_TOT * DIM];
__device__ float g_v[M_TOT * DIM];

// ---------------------------------------------------------------------------
// helpers
// ---------------------------------------------------------------------------
__device__ __forceinline__ uint32_t f2tf_u(float x) {
    uint32_t u;
    asm("cvt.rna.tf32.f32 %0, %1;" : "=r"(u) : "f"(x));
    return u;
}
__device__ __forceinline__ float tfv(float x) { return __uint_as_float(f2tf_u(x)); }

// pack (lo,hi) floats -> f16x2 (lo in low half)
__device__ __forceinline__ uint32_t h2(float lo, float hi) {
    uint32_t u;
    asm("cvt.rn.f16x2.f32 %0, %1, %2;" : "=r"(u) : "f"(hi), "f"(lo));
    return u;
}

__device__ __forceinline__ void mma8(float* c,
                                     uint32_t a0, uint32_t a1, uint32_t a2, uint32_t a3,
                                     uint32_t b0, uint32_t b1) {
    asm volatile(
        "mma.sync.aligned.m16n8k8.row.col.f32.tf32.tf32.f32 "
        "{%0,%1,%2,%3},{%4,%5,%6,%7},{%8,%9},{%0,%1,%2,%3};"
        : "+f"(c[0]), "+f"(c[1]), "+f"(c[2]), "+f"(c[3])
        : "r"(a0), "r"(a1), "r"(a2), "r"(a3), "r"(b0), "r"(b1));
}

__device__ __forceinline__ void mma16(float* c,
                                      uint32_t a0, uint32_t a1, uint32_t a2, uint32_t a3,
                                      uint32_t b0, uint32_t b1) {
    asm volatile(
        "mma.sync.aligned.m16n8k16.row.col.f32.f16.f16.f32 "
        "{%0,%1,%2,%3},{%4,%5,%6,%7},{%8,%9},{%0,%1,%2,%3};"
        : "+f"(c[0]), "+f"(c[1]), "+f"(c[2]), "+f"(c[3])
        : "r"(a0), "r"(a1), "r"(a2), "r"(a3), "r"(b0), "r"(b1));
}

__device__ __forceinline__ void ldsm_x4_t(uint32_t& r0, uint32_t& r1,
                                          uint32_t& r2, uint32_t& r3, uint32_t saddr) {
    asm volatile(
        "ldmatrix.sync.aligned.m8n8.x4.trans.shared.b16 {%0,%1,%2,%3}, [%4];"
        : "=r"(r0), "=r"(r1), "=r"(r2), "=r"(r3) : "r"(saddr));
}

// ---------------------------------------------------------------------------
// Projection GEMM (tf32 mma): Y[M,64] = X[M,1024] @ W[1024,64] + b
// q output additionally scaled by 0.125 (folded 1/sqrt(D)).
// ---------------------------------------------------------------------------
#define XS_STR 36
#define WS_STR 72
#define P_SM_X0 0
#define P_SM_X1 (128*XS_STR)
#define P_SM_W0 (2*128*XS_STR)
#define P_SM_W1 (P_SM_W0 + 32*WS_STR)
#define PROJ_SMEM_FL (P_SM_W1 + 32*WS_STR)
#define PROJ_SMEM_BYTES (PROJ_SMEM_FL * 4)

__global__ __launch_bounds__(256, 2) void proj_mma(
    const float* __restrict__ Xq, const float* __restrict__ Xk, const float* __restrict__ Xv,
    const float* __restrict__ Wq, const float* __restrict__ bq,
    const float* __restrict__ Wk, const float* __restrict__ bk,
    const float* __restrict__ Wv, const float* __restrict__ bv)
{
    const float* X; const float* W; const float* bias; float* Y;
    if (blockIdx.z == 0)      { X = Xq; W = Wq; bias = bq; Y = g_q; }
    else if (blockIdx.z == 1) { X = Xk; W = Wk; bias = bk; Y = g_k; }
    else                      { X = Xv; W = Wv; bias = bv; Y = g_v; }
    const float osc = (blockIdx.z == 0) ? 0.125f : 1.0f;

    extern __shared__ float sm[];
    const int tid  = threadIdx.x;
    const int warp = tid >> 5, lane = tid & 31;
    const int g = lane >> 2, t = lane & 3;
    const int wrow = warp * 16;
    const int row0 = blockIdx.x * 128;

    const int xr_ = tid >> 3;
    const int xc4 = (tid & 7) * 4;
    const int wr_ = tid >> 4;
    const int wc4 = (tid & 15) * 4;

    float4 xg[4], wg[2];

    #pragma unroll
    for (int i = 0; i < 4; i++)
        xg[i] = *(const float4*)(X + (size_t)(row0 + xr_ + 32*i) * HID + xc4);
    #pragma unroll
    for (int i = 0; i < 2; i++)
        wg[i] = *(const float4*)(W + (size_t)(wr_ + 16*i) * DIM + wc4);

    {
        float* xd = sm + P_SM_X0;
        float* wd = sm + P_SM_W0;
        #pragma unroll
        for (int i = 0; i < 4; i++)
            *(float4*)(xd + (xr_ + 32*i)*XS_STR + xc4) =
                make_float4(tfv(xg[i].x), tfv(xg[i].y), tfv(xg[i].z), tfv(xg[i].w));
        #pragma unroll
        for (int i = 0; i < 2; i++)
            *(float4*)(wd + (wr_ + 16*i)*WS_STR + wc4) =
                make_float4(tfv(wg[i].x), tfv(wg[i].y), tfv(wg[i].z), tfv(wg[i].w));
    }
    __syncthreads();

    float c[8][4];
    #pragma unroll
    for (int nt = 0; nt < 8; nt++)
        #pragma unroll
        for (int j = 0; j < 4; j++) c[nt][j] = 0.f;

    for (int s = 0; s < 32; s++) {
        const int cur = s & 1;
        if (s < 31) {
            const int k0 = (s + 1) * 32;
            #pragma unroll
            for (int i = 0; i < 4; i++)
                xg[i] = *(const float4*)(X + (size_t)(row0 + xr_ + 32*i) * HID + k0 + xc4);
            #pragma unroll
            for (int i = 0; i < 2; i++)
                wg[i] = *(const float4*)(W + (size_t)(k0 + wr_ + 16*i) * DIM + wc4);
        }
        const float* Xc = sm + (cur ? P_SM_X1 : P_SM_X0);
        const float* Wc = sm + (cur ? P_SM_W1 : P_SM_W0);
        const float* xa = Xc + (wrow + g) * XS_STR + t;
        const float* wb = Wc + t * WS_STR + g;

        #pragma unroll
        for (int kc = 0; kc < 4; kc++) {
            uint32_t a0 = __float_as_uint(xa[kc*8]);
            uint32_t a1 = __float_as_uint(xa[kc*8 + 8*XS_STR]);
            uint32_t a2 = __float_as_uint(xa[kc*8 + 4]);
            uint32_t a3 = __float_as_uint(xa[kc*8 + 4 + 8*XS_STR]);
            #pragma unroll
            for (int nt = 0; nt < 8; nt++) {
                uint32_t b0 = __float_as_uint(wb[(kc*8)    *WS_STR + nt*8]);
                uint32_t b1 = __float_as_uint(wb[(kc*8 + 4)*WS_STR + nt*8]);
                mma8(c[nt], a0, a1, a2, a3, b0, b1);
            }
        }
        if (s < 31) {
            float* xd = sm + (cur ? P_SM_X0 : P_SM_X1);
            float* wd = sm + (cur ? P_SM_W0 : P_SM_W1);
            #pragma unroll
            for (int i = 0; i < 4; i++)
                *(float4*)(xd + (xr_ + 32*i)*XS_STR + xc4) =
                    make_float4(tfv(xg[i].x), tfv(xg[i].y), tfv(xg[i].z), tfv(xg[i].w));
            #pragma unroll
            for (int i = 0; i < 2; i++)
                *(float4*)(wd + (wr_ + 16*i)*WS_STR + wc4) =
                    make_float4(tfv(wg[i].x), tfv(wg[i].y), tfv(wg[i].z), tfv(wg[i].w));
        }
        __syncthreads();
    }

    float* yb = Y + (size_t)(row0 + wrow + g) * DIM + 2*t;
    #pragma unroll
    for (int nt = 0; nt < 8; nt++) {
        float2 bv2 = *(const float2*)(bias + nt*8 + 2*t);
        *(float2*)(yb + nt*8)         = make_float2((c[nt][0] + bv2.x)*osc, (c[nt][1] + bv2.y)*osc);
        *(float2*)(yb + nt*8 + 8*DIM) = make_float2((c[nt][2] + bv2.x)*osc, (c[nt][3] + bv2.y)*osc);
    }
}

// ---------------------------------------------------------------------------
// Flash attention. QK^T in tf32 (fp32 smem), P·V in fp16 (fp16 smem P and V,
// ldmatrix.x4.trans for V fragments). 256 threads, 8 warps x 16 rows.
// smem ~104.5KB -> 2 CTAs/SM with __launch_bounds__(256,2).
// All SM_* are 32-bit word indices into dynamic smem.
// ---------------------------------------------------------------------------
#define QS_STR  68          // fp32 words per Q row
#define KS_STR  68          // fp32 words per K row
#define PW_STR  36          // 32-bit words per P row (fp16x2)
#define VW_STR  36          // 32-bit words per V row (fp16x2)
#define SM_QS   0
#define SM_K0   (128*QS_STR)                 // 8704
#define SM_K1   (SM_K0 + 64*KS_STR)          // 13056
#define SM_PW   (SM_K1 + 64*KS_STR)          // 17408
#define SM_V0   (SM_PW + 128*PW_STR)         // 22016
#define SM_V1   (SM_V0 + 64*VW_STR)          // 24320
#define SM_MF0  (SM_V1 + 64*VW_STR)          // 26624
#define SM_MF1  (SM_MF0 + 64)                // 26688
#define ATTN_WORDS (SM_MF1 + 64)             // 26752
#define ATTN_SMEM_BYTES (ATTN_WORDS * 4)     // 107008

__global__ __launch_bounds__(256, 2) void attn_mma(
    const int* __restrict__ mask, float* __restrict__ out)
{
    extern __shared__ float sm[];
    uint32_t* smw = (uint32_t*)sm;
    uint32_t smb;
    asm("{ .reg .u64 tt; cvta.to.shared.u64 tt, %1; cvt.u32.u64 %0, tt; }"
        : "=r"(smb) : "l"(sm));

    const int tid  = threadIdx.x;
    const int warp = tid >> 5, lane = tid & 31;
    const int g = lane >> 2, t = lane & 3;
    const int wrow = warp * 16;

    const int b  = blockIdx.y;
    const int q0 = blockIdx.x * 128;
    const float* qb = g_q + ((size_t)b * SEQ + q0) * DIM;
    const float* kb = g_k + (size_t)b * SEQ * DIM;
    const float* vb = g_v + (size_t)b * SEQ * DIM;
    const int*   mb = mask + (size_t)b * SEQ;

    // ---- load Q tile (already scaled in proj), cvt to tf32 ----
    {
        const int r = tid >> 1, d0 = (tid & 1) * 32;
        const float4* src = (const float4*)(qb + (size_t)r * DIM + d0);
        float* dst = sm + SM_QS + r * QS_STR + d0;
        #pragma unroll
        for (int i = 0; i < 8; i++) {
            float4 v = src[i];
            *(float4*)(dst + i*4) = make_float4(tfv(v.x), tfv(v.y), tfv(v.z), tfv(v.w));
        }
    }

    // ---- prefetch tile 0 ----
    const int pkey = tid >> 2;          // 0..63
    const int pd0  = (tid & 3) * 16;    // 0,16,32,48
    float4 kx[4], vx[4];
    int mreg = 0;
    {
        const float4* ks = (const float4*)(kb + (size_t)pkey * DIM + pd0);
        const float4* vs = (const float4*)(vb + (size_t)pkey * DIM + pd0);
        #pragma unroll
        for (int i = 0; i < 4; i++) { kx[i] = ks[i]; vx[i] = vs[i]; }
        if (tid < 64) mreg = mb[tid];
    }
    // stage tile 0 into buffer 0
    {
        float* kd = sm + SM_K0 + pkey * KS_STR + pd0;
        #pragma unroll
        for (int i = 0; i < 4; i++)
            *(float4*)(kd + i*4) = make_float4(tfv(kx[i].x), tfv(kx[i].y), tfv(kx[i].z), tfv(kx[i].w));
        uint32_t* vd = smw + SM_V0 + pkey * VW_STR + (pd0 >> 1);
        uint4 u0 = make_uint4(h2(vx[0].x, vx[0].y), h2(vx[0].z, vx[0].w),
                              h2(vx[1].x, vx[1].y), h2(vx[1].z, vx[1].w));
        uint4 u1 = make_uint4(h2(vx[2].x, vx[2].y), h2(vx[2].z, vx[2].w),
                              h2(vx[3].x, vx[3].y), h2(vx[3].z, vx[3].w));
        *(uint4*)(vd)     = u0;
        *(uint4*)(vd + 4) = u1;
        if (tid < 64) sm[SM_MF0 + tid] = (mreg != 0) ? 1.f : 0.f;
    }
    __syncthreads();

    float o[8][4];
    #pragma unroll
    for (int nt = 0; nt < 8; nt++)
        #pragma unroll
        for (int j = 0; j < 4; j++) o[nt][j] = 0.f;
    float m0 = -1e30f, m1 = -1e30f, l0 = 0.f, l1 = 0.f;

    const float* qa = sm + SM_QS + (wrow + g) * QS_STR + t;
    // P: A-operand read offset (words) and write offsets
    const int pA  = SM_PW + (wrow + g) * PW_STR + t;          // + kc*8 (+4)
    const int pA8 = pA + 8 * PW_STR;
    // ldmatrix lane constants
    const int ltile = lane >> 3;
    const int krow  = ((ltile & 1) << 3) + (lane & 7);
    const int vcol4 = (ltile >> 1) << 2;

    for (int kt = 0; kt < 64; kt++) {
        const int cur = kt & 1;
        if (kt < 63) {
            const float4* ks = (const float4*)(kb + (size_t)((kt+1)*64 + pkey) * DIM + pd0);
            const float4* vs = (const float4*)(vb + (size_t)((kt+1)*64 + pkey) * DIM + pd0);
            #pragma unroll
            for (int i = 0; i < 4; i++) { kx[i] = ks[i]; vx[i] = vs[i]; }
            if (tid < 64) mreg = mb[(kt+1)*64 + tid];
        }
        const float* Kc = sm + (cur ? SM_K1 : SM_K0);
        const float* Mc = sm + (cur ? SM_MF1 : SM_MF0);
        const uint32_t vbase = smb + 4u * ((cur ? SM_V1 : SM_V0) + krow * VW_STR + vcol4);

        // ---- S = Q @ K^T (tf32) ----
        float c[8][4];
        #pragma unroll
        for (int nt = 0; nt < 8; nt++)
            #pragma unroll
            for (int j = 0; j < 4; j++) c[nt][j] = 0.f;

        const float* kbp = Kc + g * KS_STR + t;
        #pragma unroll
        for (int kc = 0; kc < 8; kc++) {
            uint32_t a0 = __float_as_uint(qa[kc*8]);
            uint32_t a1 = __float_as_uint(qa[kc*8 + 8*QS_STR]);
            uint32_t a2 = __float_as_uint(qa[kc*8 + 4]);
            uint32_t a3 = __float_as_uint(qa[kc*8 + 4 + 8*QS_STR]);
            #pragma unroll
            for (int nt = 0; nt < 8; nt++) {
                uint32_t b0 = __float_as_uint(kbp[nt*8*KS_STR + kc*8]);
                uint32_t b1 = __float_as_uint(kbp[nt*8*KS_STR + kc*8 + 4]);
                mma8(c[nt], a0, a1, a2, a3, b0, b1);
            }
        }

        // ---- mask + row max ----
        float mx0 = -1e30f, mx1 = -1e30f;
        #pragma unroll
        for (int nt = 0; nt < 8; nt++) {
            float2 mv = *(const float2*)(Mc + nt*8 + 2*t);
            if (mv.x == 0.f) { c[nt][0] = -1e9f; c[nt][2] = -1e9f; }
            if (mv.y == 0.f) { c[nt][1] = -1e9f; c[nt][3] = -1e9f; }
            mx0 = fmaxf(mx0, fmaxf(c[nt][0], c[nt][1]));
            mx1 = fmaxf(mx1, fmaxf(c[nt][2], c[nt][3]));
        }
        mx0 = fmaxf(mx0, __shfl_xor_sync(0xffffffffu, mx0, 1));
        mx0 = fmaxf(mx0, __shfl_xor_sync(0xffffffffu, mx0, 2));
        mx1 = fmaxf(mx1, __shfl_xor_sync(0xffffffffu, mx1, 1));
        mx1 = fmaxf(mx1, __shfl_xor_sync(0xffffffffu, mx1, 2));

        const float mn0 = fmaxf(m0, mx0), mn1 = fmaxf(m1, mx1);

        float s0 = 0.f, s1 = 0.f;
        #pragma unroll
        for (int nt = 0; nt < 8; nt++) {
            c[nt][0] = __expf(c[nt][0] - mn0);
            c[nt][1] = __expf(c[nt][1] - mn0);
            c[nt][2] = __expf(c[nt][2] - mn1);
            c[nt][3] = __expf(c[nt][3] - mn1);
            s0 += c[nt][0] + c[nt][1];
            s1 += c[nt][2] + c[nt][3];
        }
        s0 += __shfl_xor_sync(0xffffffffu, s0, 1);
        s0 += __shfl_xor_sync(0xffffffffu, s0, 2);
        s1 += __shfl_xor_sync(0xffffffffu, s1, 1);
        s1 += __shfl_xor_sync(0xffffffffu, s1, 2);

        const float co0 = __expf(m0 - mn0), co1 = __expf(m1 - mn1);
        m0 = mn0; m1 = mn1;
        l0 = l0 * co0 + s0;
        l1 = l1 * co1 + s1;

        // ---- write P (fp16x2), rescale O ----
        #pragma unroll
        for (int nt = 0; nt < 8; nt++) {
            smw[pA  + nt*4] = h2(c[nt][0], c[nt][1]);
            smw[pA8 + nt*4] = h2(c[nt][2], c[nt][3]);
            o[nt][0] *= co0; o[nt][1] *= co0;
            o[nt][2] *= co1; o[nt][3] *= co1;
        }
        __syncwarp();

        // ---- O += P @ V (fp16 mma, V via ldmatrix.trans) ----
        #pragma unroll
        for (int kc = 0; kc < 4; kc++) {
            uint32_t a0 = smw[pA  + kc*8];
            uint32_t a1 = smw[pA8 + kc*8];
            uint32_t a2 = smw[pA  + kc*8 + 4];
            uint32_t a3 = smw[pA8 + kc*8 + 4];
            #pragma unroll
            for (int ntp = 0; ntp < 4; ntp++) {
                uint32_t b0, b1, b2, b3;
                ldsm_x4_t(b0, b1, b2, b3,
                          vbase + 4u * (kc * 16 * VW_STR + ntp * 8));
                mma16(o[2*ntp],     a0, a1, a2, a3, b0, b1);
                mma16(o[2*ntp + 1], a0, a1, a2, a3, b2, b3);
            }
        }

        // ---- stage next tile ----
        if (kt < 63) {
            float* kd = sm + (cur ? SM_K0 : SM_K1) + pkey * KS_STR + pd0;
            #pragma unroll
            for (int i = 0; i < 4; i++)
                *(float4*)(kd + i*4) = make_float4(tfv(kx[i].x), tfv(kx[i].y), tfv(kx[i].z), tfv(kx[i].w));
            uint32_t* vd = smw + (cur ? SM_V0 : SM_V1) + pkey * VW_STR + (pd0 >> 1);
            uint4 u0 = make_uint4(h2(vx[0].x, vx[0].y), h2(vx[0].z, vx[0].w),
                                  h2(vx[1].x, vx[1].y), h2(vx[1].z, vx[1].w));
            uint4 u1 = make_uint4(h2(vx[2].x, vx[2].y), h2(vx[2].z, vx[2].w),
                                  h2(vx[3].x, vx[3].y), h2(vx[3].z, vx[3].w));
            *(uint4*)(vd)     = u0;
            *(uint4*)(vd + 4) = u1;
            if (tid < 64) sm[(cur ? SM_MF0 : SM_MF1) + tid] = (mreg != 0) ? 1.f : 0.f;
        }
        __syncthreads();
    }

    // ---- epilogue: normalize + store ----
    const float i0 = 1.f / l0, i1 = 1.f / l1;
    float* ob = out + ((size_t)b * SEQ + q0 + wrow + g) * DIM + 2*t;
    #pragma unroll
    for (int nt = 0; nt < 8; nt++) {
        *(float2*)(ob + nt*8)         = make_float2(o[nt][0]*i0, o[nt][1]*i0);
        *(float2*)(ob + nt*8 + 8*DIM) = make_float2(o[nt][2]*i1, o[nt][3]*i1);
    }
}

// ---------------------------------------------------------------------------
extern "C" void kernel_launch(void* const* d_in, const int* in_sizes, int n_in,
                              void* d_out, int out_size)
{
    const float* query = (const float*)d_in[0];
    const float* key_  = (const float*)d_in[1];
    const float* value = (const float*)d_in[2];
    const int*   mask  = (const int*)d_in[3];
    const float* Wq = (const float*)d_in[4];
    const float* bq = (const float*)d_in[5];
    const float* Wk = (const float*)d_in[6];
    const float* bk = (const float*)d_in[7];
    const float* Wv = (const float*)d_in[8];
    const float* bv = (const float*)d_in[9];
    float* out = (float*)d_out;

    cudaFuncSetAttribute(proj_mma, cudaFuncAttributeMaxDynamicSharedMemorySize,
                         PROJ_SMEM_BYTES);
    cudaFuncSetAttribute(attn_mma, cudaFuncAttributeMaxDynamicSharedMemorySize,
                         ATTN_SMEM_BYTES);

    dim3 gp(M_TOT / 128, 1, 3);
    proj_mma<<<gp, 256, PROJ_SMEM_BYTES>>>(query, key_, value,
                                           Wq, bq, Wk, bk, Wv, bv);

    dim3 ga(SEQ / 128, BATCH);
    attn_mma<<<ga, 256, ATTN_SMEM_BYTES>>>(mask, out);
}

// round 5
// speedup vs baseline: 4.5610x; 1.4299x over previous
#include <cuda_runtime.h>
#include <stdint.h>

// Problem: B=4, S=4096, H=1024, D=64
#define BATCH 4
#define SEQ   4096
#define HID   1024
#define DIM   64
#define M_TOT (BATCH*SEQ)   // 16384

// Scratch: q,k stored pre-rounded to tf32 (q also pre-scaled by 1/8); v as fp16
__device__ float    g_q[M_TOT * DIM];
__device__ float    g_k[M_TOT * DIM];
__device__ uint16_t g_vh[M_TOT * DIM];

// ---------------------------------------------------------------------------
// helpers
// ---------------------------------------------------------------------------
__device__ __forceinline__ uint32_t f2tf_u(float x) {
    uint32_t u;
    asm("cvt.rna.tf32.f32 %0, %1;" : "=r"(u) : "f"(x));
    return u;
}
__device__ __forceinline__ float tfv(float x) { return __uint_as_float(f2tf_u(x)); }

// pack (lo,hi) floats -> f16x2 (lo in low half)
__device__ __forceinline__ uint32_t h2(float lo, float hi) {
    uint32_t u;
    asm("cvt.rn.f16x2.f32 %0, %1, %2;" : "=r"(u) : "f"(hi), "f"(lo));
    return u;
}

__device__ __forceinline__ void mma8(float* c,
                                     uint32_t a0, uint32_t a1, uint32_t a2, uint32_t a3,
                                     uint32_t b0, uint32_t b1) {
    asm volatile(
        "mma.sync.aligned.m16n8k8.row.col.f32.tf32.tf32.f32 "
        "{%0,%1,%2,%3},{%4,%5,%6,%7},{%8,%9},{%0,%1,%2,%3};"
        : "+f"(c[0]), "+f"(c[1]), "+f"(c[2]), "+f"(c[3])
        : "r"(a0), "r"(a1), "r"(a2), "r"(a3), "r"(b0), "r"(b1));
}

__device__ __forceinline__ void mma16(float* c,
                                      uint32_t a0, uint32_t a1, uint32_t a2, uint32_t a3,
                                      uint32_t b0, uint32_t b1) {
    asm volatile(
        "mma.sync.aligned.m16n8k16.row.col.f32.f16.f16.f32 "
        "{%0,%1,%2,%3},{%4,%5,%6,%7},{%8,%9},{%0,%1,%2,%3};"
        : "+f"(c[0]), "+f"(c[1]), "+f"(c[2]), "+f"(c[3])
        : "r"(a0), "r"(a1), "r"(a2), "r"(a3), "r"(b0), "r"(b1));
}

__device__ __forceinline__ void ldsm_x4_t(uint32_t& r0, uint32_t& r1,
                                          uint32_t& r2, uint32_t& r3, uint32_t saddr) {
    asm volatile(
        "ldmatrix.sync.aligned.m8n8.x4.trans.shared.b16 {%0,%1,%2,%3}, [%4];"
        : "=r"(r0), "=r"(r1), "=r"(r2), "=r"(r3) : "r"(saddr));
}

__device__ __forceinline__ void cpa16(uint32_t saddr, const void* gaddr) {
    asm volatile("cp.async.ca.shared.global [%0], [%1], 16;"
                 :: "r"(saddr), "l"(gaddr) : "memory");
}
__device__ __forceinline__ void cpa_commit() {
    asm volatile("cp.async.commit_group;" ::: "memory");
}
__device__ __forceinline__ void cpa_wait0() {
    asm volatile("cp.async.wait_group 0;" ::: "memory");
}

// ---------------------------------------------------------------------------
// Projection GEMM (tf32 mma): Y[M,64] = X[M,1024] @ W[1024,64] + b
// Outputs: z=0 -> g_q (tf32-rounded, *0.125), z=1 -> g_k (tf32), z=2 -> g_vh (fp16)
// ---------------------------------------------------------------------------
#define XS_STR 36
#define WS_STR 72
#define P_SM_X0 0
#define P_SM_X1 (128*XS_STR)
#define P_SM_W0 (2*128*XS_STR)
#define P_SM_W1 (P_SM_W0 + 32*WS_STR)
#define PROJ_SMEM_FL (P_SM_W1 + 32*WS_STR)
#define PROJ_SMEM_BYTES (PROJ_SMEM_FL * 4)

__global__ __launch_bounds__(256, 2) void proj_mma(
    const float* __restrict__ Xq, const float* __restrict__ Xk, const float* __restrict__ Xv,
    const float* __restrict__ Wq, const float* __restrict__ bq,
    const float* __restrict__ Wk, const float* __restrict__ bk,
    const float* __restrict__ Wv, const float* __restrict__ bv)
{
    const float* X; const float* W; const float* bias;
    if (blockIdx.z == 0)      { X = Xq; W = Wq; bias = bq; }
    else if (blockIdx.z == 1) { X = Xk; W = Wk; bias = bk; }
    else                      { X = Xv; W = Wv; bias = bv; }

    extern __shared__ float sm[];
    const int tid  = threadIdx.x;
    const int warp = tid >> 5, lane = tid & 31;
    const int g = lane >> 2, t = lane & 3;
    const int wrow = warp * 16;
    const int row0 = blockIdx.x * 128;

    const int xr_ = tid >> 3;
    const int xc4 = (tid & 7) * 4;
    const int wr_ = tid >> 4;
    const int wc4 = (tid & 15) * 4;

    float4 xg[4], wg[2];

    #pragma unroll
    for (int i = 0; i < 4; i++)
        xg[i] = *(const float4*)(X + (size_t)(row0 + xr_ + 32*i) * HID + xc4);
    #pragma unroll
    for (int i = 0; i < 2; i++)
        wg[i] = *(const float4*)(W + (size_t)(wr_ + 16*i) * DIM + wc4);

    {
        float* xd = sm + P_SM_X0;
        float* wd = sm + P_SM_W0;
        #pragma unroll
        for (int i = 0; i < 4; i++)
            *(float4*)(xd + (xr_ + 32*i)*XS_STR + xc4) =
                make_float4(tfv(xg[i].x), tfv(xg[i].y), tfv(xg[i].z), tfv(xg[i].w));
        #pragma unroll
        for (int i = 0; i < 2; i++)
            *(float4*)(wd + (wr_ + 16*i)*WS_STR + wc4) =
                make_float4(tfv(wg[i].x), tfv(wg[i].y), tfv(wg[i].z), tfv(wg[i].w));
    }
    __syncthreads();

    float c[8][4];
    #pragma unroll
    for (int nt = 0; nt < 8; nt++)
        #pragma unroll
        for (int j = 0; j < 4; j++) c[nt][j] = 0.f;

    for (int s = 0; s < 32; s++) {
        const int cur = s & 1;
        if (s < 31) {
            const int k0 = (s + 1) * 32;
            #pragma unroll
            for (int i = 0; i < 4; i++)
                xg[i] = *(const float4*)(X + (size_t)(row0 + xr_ + 32*i) * HID + k0 + xc4);
            #pragma unroll
            for (int i = 0; i < 2; i++)
                wg[i] = *(const float4*)(W + (size_t)(k0 + wr_ + 16*i) * DIM + wc4);
        }
        const float* Xc = sm + (cur ? P_SM_X1 : P_SM_X0);
        const float* Wc = sm + (cur ? P_SM_W1 : P_SM_W0);
        const float* xa = Xc + (wrow + g) * XS_STR + t;
        const float* wb = Wc + t * WS_STR + g;

        #pragma unroll
        for (int kc = 0; kc < 4; kc++) {
            uint32_t a0 = __float_as_uint(xa[kc*8]);
            uint32_t a1 = __float_as_uint(xa[kc*8 + 8*XS_STR]);
            uint32_t a2 = __float_as_uint(xa[kc*8 + 4]);
            uint32_t a3 = __float_as_uint(xa[kc*8 + 4 + 8*XS_STR]);
            #pragma unroll
            for (int nt = 0; nt < 8; nt++) {
                uint32_t b0 = __float_as_uint(wb[(kc*8)    *WS_STR + nt*8]);
                uint32_t b1 = __float_as_uint(wb[(kc*8 + 4)*WS_STR + nt*8]);
                mma8(c[nt], a0, a1, a2, a3, b0, b1);
            }
        }
        if (s < 31) {
            float* xd = sm + (cur ? P_SM_X0 : P_SM_X1);
            float* wd = sm + (cur ? P_SM_W0 : P_SM_W1);
            #pragma unroll
            for (int i = 0; i < 4; i++)
                *(float4*)(xd + (xr_ + 32*i)*XS_STR + xc4) =
                    make_float4(tfv(xg[i].x), tfv(xg[i].y), tfv(xg[i].z), tfv(xg[i].w));
            #pragma unroll
            for (int i = 0; i < 2; i++)
                *(float4*)(wd + (wr_ + 16*i)*WS_STR + wc4) =
                    make_float4(tfv(wg[i].x), tfv(wg[i].y), tfv(wg[i].z), tfv(wg[i].w));
        }
        __syncthreads();
    }

    const int r = row0 + wrow + g;
    if (blockIdx.z == 2) {
        uint32_t* vb32 = (uint32_t*)g_vh;   // 2 halves per u32; row stride 32 u32
        #pragma unroll
        for (int nt = 0; nt < 8; nt++) {
            float2 b2 = *(const float2*)(bias + nt*8 + 2*t);
            vb32[(size_t)r       * 32 + nt*4 + t] = h2(c[nt][0] + b2.x, c[nt][1] + b2.y);
            vb32[(size_t)(r + 8) * 32 + nt*4 + t] = h2(c[nt][2] + b2.x, c[nt][3] + b2.y);
        }
    } else {
        float* Y = (blockIdx.z == 0) ? g_q : g_k;
        const float osc = (blockIdx.z == 0) ? 0.125f : 1.0f;
        float* yb = Y + (size_t)r * DIM + 2*t;
        #pragma unroll
        for (int nt = 0; nt < 8; nt++) {
            float2 b2 = *(const float2*)(bias + nt*8 + 2*t);
            *(float2*)(yb + nt*8) =
                make_float2(tfv((c[nt][0] + b2.x)*osc), tfv((c[nt][1] + b2.y)*osc));
            *(float2*)(yb + nt*8 + 8*DIM) =
                make_float2(tfv((c[nt][2] + b2.x)*osc), tfv((c[nt][3] + b2.y)*osc));
        }
    }
}

// ---------------------------------------------------------------------------
// Flash attention. 64 Q-rows per CTA, 128 threads (4 warps x 16 rows).
// Q fragments hoisted to registers. K/V/mask staged with cp.async double
// buffering (tile j -> buffer (j+1)&1; Q staging aliases K buffer 0).
// P goes straight from QK accumulators into fp16 A-fragments (no smem).
// ---------------------------------------------------------------------------
#define KST 68                               // fp32 words per K row
#define VST 36                               // u32 words per V row (fp16x2)
#define SM_K0  0
#define SM_K1  (64*KST)                      // 4352
#define SM_V0  (2*64*KST)                    // 8704
#define SM_V1  (SM_V0 + 64*VST)              // 11008
#define SM_MK0 (SM_V1 + 64*VST)              // 13312
#define SM_MK1 (SM_MK0 + 64)                 // 13376
#define ATTN_WORDS (SM_MK1 + 64)             // 13440
#define ATTN_SMEM_BYTES (ATTN_WORDS * 4)     // 53760

__global__ __launch_bounds__(128, 3) void attn_mma(
    const int* __restrict__ mask, float* __restrict__ out)
{
    extern __shared__ float sm[];
    uint32_t* smw = (uint32_t*)sm;
    uint32_t smb;
    asm("{ .reg .u64 tt; cvta.to.shared.u64 tt, %1; cvt.u32.u64 %0, tt; }"
        : "=r"(smb) : "l"(sm));

    const int tid  = threadIdx.x;
    const int warp = tid >> 5, lane = tid & 31;
    const int g = lane >> 2, t = lane & 3;
    const int wrow = warp * 16;

    const int b  = blockIdx.y;
    const int q0 = blockIdx.x * 64;
    const float*    qb = g_q + ((size_t)b * SEQ + q0) * DIM;
    const float*    kb = g_k + (size_t)b * SEQ * DIM;
    const uint16_t* vb = g_vh + (size_t)b * SEQ * DIM;
    const int*      mb = mask + (size_t)b * SEQ;

    // ---- prologue: stage Q into K0 region (64 rows x 16 chunks = 1024) ----
    #pragma unroll
    for (int i = 0; i < 8; i++) {
        const int c  = tid + i*128;          // 0..1023
        const int row = c >> 4;              // 0..63
        const int d4  = (c & 15) << 2;       // 0..60 (floats)
        cpa16(smb + 4u*(SM_K0 + row*KST + d4), qb + (size_t)row*DIM + d4);
    }
    cpa_commit();
    // tile 0 -> K1/V1/MK1
    {
        #pragma unroll
        for (int i = 0; i < 8; i++) {
            const int c = tid + i*128;                 // 1024 chunks K
            const int key = c >> 4, d4 = (c & 15) << 2;
            cpa16(smb + 4u*(SM_K1 + key*KST + d4), kb + (size_t)key*DIM + d4);
        }
        #pragma unroll
        for (int i = 0; i < 4; i++) {
            const int c = tid + i*128;                 // 512 chunks V
            const int key = c >> 3, w4 = (c & 7) << 2;
            cpa16(smb + 4u*(SM_V1 + key*VST + w4), vb + (size_t)key*DIM + w4*2);
        }
        if (tid < 16)
            cpa16(smb + 4u*(SM_MK1 + tid*4), mb + tid*4);
    }
    cpa_commit();
    cpa_wait0();
    __syncthreads();

    // ---- hoist Q fragments ----
    uint32_t qf[8][4];
    {
        const uint32_t* qa = smw + SM_K0 + (wrow + g) * KST + t;
        #pragma unroll
        for (int kc = 0; kc < 8; kc++) {
            qf[kc][0] = qa[kc*8];
            qf[kc][1] = qa[kc*8 + 8*KST];
            qf[kc][2] = qa[kc*8 + 4];
            qf[kc][3] = qa[kc*8 + 4 + 8*KST];
        }
    }
    __syncthreads();   // everyone done reading K0 region before tile1 staged

    float o[8][4];
    #pragma unroll
    for (int nt = 0; nt < 8; nt++)
        #pragma unroll
        for (int j = 0; j < 4; j++) o[nt][j] = 0.f;
    float m0 = -1e30f, m1 = -1e30f, l0 = 0.f, l1 = 0.f;

    // ldmatrix lane mapping (validated R3 layout)
    const int ltile = lane >> 3;
    const int krow  = ((ltile & 1) << 3) + (lane & 7);
    const int vcol4 = (ltile >> 1) << 2;

    for (int kt = 0; kt < 64; kt++) {
        // tile kt lives in buffer (kt+1)&1
        const int buf = (kt + 1) & 1;
        cpa_wait0();
        __syncthreads();

        // stage tile kt+1 into buffer kt&1
        if (kt < 63) {
            const int nbuf = kt & 1;
            const int kbw = nbuf ? SM_K1 : SM_K0;
            const int vbw = nbuf ? SM_V1 : SM_V0;
            const int mbw = nbuf ? SM_MK1 : SM_MK0;
            const size_t kofs = (size_t)(kt + 1) * 64;
            #pragma unroll
            for (int i = 0; i < 8; i++) {
                const int c = tid + i*128;
                const int key = c >> 4, d4 = (c & 15) << 2;
                cpa16(smb + 4u*(kbw + key*KST + d4), kb + (kofs + key)*DIM + d4);
            }
            #pragma unroll
            for (int i = 0; i < 4; i++) {
                const int c = tid + i*128;
                const int key = c >> 3, w4 = (c & 7) << 2;
                cpa16(smb + 4u*(vbw + key*VST + w4), vb + (kofs + key)*DIM + w4*2);
            }
            if (tid < 16)
                cpa16(smb + 4u*(mbw + tid*4), mb + kofs + tid*4);
            cpa_commit();
        }

        const uint32_t* Kc = smw + (buf ? SM_K1 : SM_K0);
        const int*      Mc = (const int*)(smw + (buf ? SM_MK1 : SM_MK0));
        const uint32_t  vba = smb + 4u*((buf ? SM_V1 : SM_V0) + krow*VST + vcol4);

        // ---- S = Q @ K^T (tf32; operands pre-rounded) ----
        float c[8][4];
        #pragma unroll
        for (int nt = 0; nt < 8; nt++)
            #pragma unroll
            for (int j = 0; j < 4; j++) c[nt][j] = 0.f;

        const uint32_t* kbp = Kc + g * KST + t;
        #pragma unroll
        for (int kc = 0; kc < 8; kc++) {
            #pragma unroll
            for (int nt = 0; nt < 8; nt++) {
                uint32_t b0 = kbp[nt*8*KST + kc*8];
                uint32_t b1 = kbp[nt*8*KST + kc*8 + 4];
                mma8(c[nt], qf[kc][0], qf[kc][1], qf[kc][2], qf[kc][3], b0, b1);
            }
        }

        // ---- mask + row max ----
        float mx0 = -1e30f, mx1 = -1e30f;
        #pragma unroll
        for (int nt = 0; nt < 8; nt++) {
            int2 mv = *(const int2*)(Mc + nt*8 + 2*t);
            if (mv.x == 0) { c[nt][0] = -1e9f; c[nt][2] = -1e9f; }
            if (mv.y == 0) { c[nt][1] = -1e9f; c[nt][3] = -1e9f; }
            mx0 = fmaxf(mx0, fmaxf(c[nt][0], c[nt][1]));
            mx1 = fmaxf(mx1, fmaxf(c[nt][2], c[nt][3]));
        }
        mx0 = fmaxf(mx0, __shfl_xor_sync(0xffffffffu, mx0, 1));
        mx0 = fmaxf(mx0, __shfl_xor_sync(0xffffffffu, mx0, 2));
        mx1 = fmaxf(mx1, __shfl_xor_sync(0xffffffffu, mx1, 1));
        mx1 = fmaxf(mx1, __shfl_xor_sync(0xffffffffu, mx1, 2));

        const float mn0 = fmaxf(m0, mx0), mn1 = fmaxf(m1, mx1);

        float s0 = 0.f, s1 = 0.f;
        #pragma unroll
        for (int nt = 0; nt < 8; nt++) {
            c[nt][0] = __expf(c[nt][0] - mn0);
            c[nt][1] = __expf(c[nt][1] - mn0);
            c[nt][2] = __expf(c[nt][2] - mn1);
            c[nt][3] = __expf(c[nt][3] - mn1);
            s0 += c[nt][0] + c[nt][1];
            s1 += c[nt][2] + c[nt][3];
        }
        s0 += __shfl_xor_sync(0xffffffffu, s0, 1);
        s0 += __shfl_xor_sync(0xffffffffu, s0, 2);
        s1 += __shfl_xor_sync(0xffffffffu, s1, 1);
        s1 += __shfl_xor_sync(0xffffffffu, s1, 2);

        const float co0 = __expf(m0 - mn0), co1 = __expf(m1 - mn1);
        m0 = mn0; m1 = mn1;
        l0 = l0 * co0 + s0;
        l1 = l1 * co1 + s1;

        #pragma unroll
        for (int nt = 0; nt < 8; nt++) {
            o[nt][0] *= co0; o[nt][1] *= co0;
            o[nt][2] *= co1; o[nt][3] *= co1;
        }

        // ---- O += P @ V : P fragments built directly from accumulators ----
        #pragma unroll
        for (int kc = 0; kc < 4; kc++) {
            uint32_t a0 = h2(c[2*kc][0],   c[2*kc][1]);
            uint32_t a1 = h2(c[2*kc][2],   c[2*kc][3]);
            uint32_t a2 = h2(c[2*kc+1][0], c[2*kc+1][1]);
            uint32_t a3 = h2(c[2*kc+1][2], c[2*kc+1][3]);
            #pragma unroll
            for (int ntp = 0; ntp < 4; ntp++) {
                uint32_t b0, b1, b2, b3;
                ldsm_x4_t(b0, b1, b2, b3, vba + 4u*(kc*16*VST + ntp*8));
                mma16(o[2*ntp],     a0, a1, a2, a3, b0, b1);
                mma16(o[2*ntp + 1], a0, a1, a2, a3, b2, b3);
            }
        }
    }

    // ---- epilogue: normalize + store ----
    const float i0 = 1.f / l0, i1 = 1.f / l1;
    float* ob = out + ((size_t)b * SEQ + q0 + wrow + g) * DIM + 2*t;
    #pragma unroll
    for (int nt = 0; nt < 8; nt++) {
        *(float2*)(ob + nt*8)         = make_float2(o[nt][0]*i0, o[nt][1]*i0);
        *(float2*)(ob + nt*8 + 8*DIM) = make_float2(o[nt][2]*i1, o[nt][3]*i1);
    }
}

// ---------------------------------------------------------------------------
extern "C" void kernel_launch(void* const* d_in, const int* in_sizes, int n_in,
                              void* d_out, int out_size)
{
    const float* query = (const float*)d_in[0];
    const float* key_  = (const float*)d_in[1];
    const float* value = (const float*)d_in[2];
    const int*   mask  = (const int*)d_in[3];
    const float* Wq = (const float*)d_in[4];
    const float* bq = (const float*)d_in[5];
    const float* Wk = (const float*)d_in[6];
    const float* bk = (const float*)d_in[7];
    const float* Wv = (const float*)d_in[8];
    const float* bv = (const float*)d_in[9];
    float* out = (float*)d_out;

    cudaFuncSetAttribute(proj_mma, cudaFuncAttributeMaxDynamicSharedMemorySize,
                         PROJ_SMEM_BYTES);
    cudaFuncSetAttribute(attn_mma, cudaFuncAttributeMaxDynamicSharedMemorySize,
                         ATTN_SMEM_BYTES);

    dim3 gp(M_TOT / 128, 1, 3);
    proj_mma<<<gp, 256, PROJ_SMEM_BYTES>>>(query, key_, value,
                                           Wq, bq, Wk, bk, Wv, bv);

    dim3 ga(SEQ / 64, BATCH);
    attn_mma<<<ga, 128, ATTN_SMEM_BYTES>>>(mask, out);
}

// round 6
// speedup vs baseline: 5.1873x; 1.1373x over previous
#include <cuda_runtime.h>
#include <stdint.h>

// Problem: B=4, S=4096, H=1024, D=64
#define BATCH 4
#define SEQ   4096
#define HID   1024
#define DIM   64
#define M_TOT (BATCH*SEQ)   // 16384

// Scratch: projected q (pre-scaled 1/8), k, v — all fp16
__device__ uint16_t g_qh[M_TOT * DIM];
__device__ uint16_t g_kh[M_TOT * DIM];
__device__ uint16_t g_vh[M_TOT * DIM];

// ---------------------------------------------------------------------------
// helpers
// ---------------------------------------------------------------------------
__device__ __forceinline__ uint32_t f2tf_u(float x) {
    uint32_t u;
    asm("cvt.rna.tf32.f32 %0, %1;" : "=r"(u) : "f"(x));
    return u;
}
__device__ __forceinline__ float tfv(float x) { return __uint_as_float(f2tf_u(x)); }

// pack (lo,hi) floats -> f16x2 (lo in low half)
__device__ __forceinline__ uint32_t h2(float lo, float hi) {
    uint32_t u;
    asm("cvt.rn.f16x2.f32 %0, %1, %2;" : "=r"(u) : "f"(hi), "f"(lo));
    return u;
}

__device__ __forceinline__ void mma8(float* c,
                                     uint32_t a0, uint32_t a1, uint32_t a2, uint32_t a3,
                                     uint32_t b0, uint32_t b1) {
    asm volatile(
        "mma.sync.aligned.m16n8k8.row.col.f32.tf32.tf32.f32 "
        "{%0,%1,%2,%3},{%4,%5,%6,%7},{%8,%9},{%0,%1,%2,%3};"
        : "+f"(c[0]), "+f"(c[1]), "+f"(c[2]), "+f"(c[3])
        : "r"(a0), "r"(a1), "r"(a2), "r"(a3), "r"(b0), "r"(b1));
}

__device__ __forceinline__ void mma16(float* c,
                                      uint32_t a0, uint32_t a1, uint32_t a2, uint32_t a3,
                                      uint32_t b0, uint32_t b1) {
    asm volatile(
        "mma.sync.aligned.m16n8k16.row.col.f32.f16.f16.f32 "
        "{%0,%1,%2,%3},{%4,%5,%6,%7},{%8,%9},{%0,%1,%2,%3};"
        : "+f"(c[0]), "+f"(c[1]), "+f"(c[2]), "+f"(c[3])
        : "r"(a0), "r"(a1), "r"(a2), "r"(a3), "r"(b0), "r"(b1));
}

__device__ __forceinline__ void ldsm_x4(uint32_t& r0, uint32_t& r1,
                                        uint32_t& r2, uint32_t& r3, uint32_t saddr) {
    asm volatile(
        "ldmatrix.sync.aligned.m8n8.x4.shared.b16 {%0,%1,%2,%3}, [%4];"
        : "=r"(r0), "=r"(r1), "=r"(r2), "=r"(r3) : "r"(saddr));
}

__device__ __forceinline__ void ldsm_x4_t(uint32_t& r0, uint32_t& r1,
                                          uint32_t& r2, uint32_t& r3, uint32_t saddr) {
    asm volatile(
        "ldmatrix.sync.aligned.m8n8.x4.trans.shared.b16 {%0,%1,%2,%3}, [%4];"
        : "=r"(r0), "=r"(r1), "=r"(r2), "=r"(r3) : "r"(saddr));
}

__device__ __forceinline__ void cpa16(uint32_t saddr, const void* gaddr) {
    asm volatile("cp.async.ca.shared.global [%0], [%1], 16;"
                 :: "r"(saddr), "l"(gaddr) : "memory");
}
__device__ __forceinline__ void cpa_commit() {
    asm volatile("cp.async.commit_group;" ::: "memory");
}
__device__ __forceinline__ void cpa_wait0() {
    asm volatile("cp.async.wait_group 0;" ::: "memory");
}

// ---------------------------------------------------------------------------
// Projection GEMM (tf32 mma): Y[M,64] = X[M,1024] @ W[1024,64] + b
// Epilogue rounds to fp16: z=0 -> g_qh (*0.125), z=1 -> g_kh, z=2 -> g_vh
// ---------------------------------------------------------------------------
#define XS_STR 36
#define WS_STR 72
#define P_SM_X0 0
#define P_SM_X1 (128*XS_STR)
#define P_SM_W0 (2*128*XS_STR)
#define P_SM_W1 (P_SM_W0 + 32*WS_STR)
#define PROJ_SMEM_FL (P_SM_W1 + 32*WS_STR)
#define PROJ_SMEM_BYTES (PROJ_SMEM_FL * 4)

__global__ __launch_bounds__(256, 2) void proj_mma(
    const float* __restrict__ Xq, const float* __restrict__ Xk, const float* __restrict__ Xv,
    const float* __restrict__ Wq, const float* __restrict__ bq,
    const float* __restrict__ Wk, const float* __restrict__ bk,
    const float* __restrict__ Wv, const float* __restrict__ bv)
{
    const float* X; const float* W; const float* bias;
    if (blockIdx.z == 0)      { X = Xq; W = Wq; bias = bq; }
    else if (blockIdx.z == 1) { X = Xk; W = Wk; bias = bk; }
    else                      { X = Xv; W = Wv; bias = bv; }

    extern __shared__ float sm[];
    const int tid  = threadIdx.x;
    const int warp = tid >> 5, lane = tid & 31;
    const int g = lane >> 2, t = lane & 3;
    const int wrow = warp * 16;
    const int row0 = blockIdx.x * 128;

    const int xr_ = tid >> 3;
    const int xc4 = (tid & 7) * 4;
    const int wr_ = tid >> 4;
    const int wc4 = (tid & 15) * 4;

    float4 xg[4], wg[2];

    #pragma unroll
    for (int i = 0; i < 4; i++)
        xg[i] = *(const float4*)(X + (size_t)(row0 + xr_ + 32*i) * HID + xc4);
    #pragma unroll
    for (int i = 0; i < 2; i++)
        wg[i] = *(const float4*)(W + (size_t)(wr_ + 16*i) * DIM + wc4);

    {
        float* xd = sm + P_SM_X0;
        float* wd = sm + P_SM_W0;
        #pragma unroll
        for (int i = 0; i < 4; i++)
            *(float4*)(xd + (xr_ + 32*i)*XS_STR + xc4) =
                make_float4(tfv(xg[i].x), tfv(xg[i].y), tfv(xg[i].z), tfv(xg[i].w));
        #pragma unroll
        for (int i = 0; i < 2; i++)
            *(float4*)(wd + (wr_ + 16*i)*WS_STR + wc4) =
                make_float4(tfv(wg[i].x), tfv(wg[i].y), tfv(wg[i].z), tfv(wg[i].w));
    }
    __syncthreads();

    float c[8][4];
    #pragma unroll
    for (int nt = 0; nt < 8; nt++)
        #pragma unroll
        for (int j = 0; j < 4; j++) c[nt][j] = 0.f;

    for (int s = 0; s < 32; s++) {
        const int cur = s & 1;
        if (s < 31) {
            const int k0 = (s + 1) * 32;
            #pragma unroll
            for (int i = 0; i < 4; i++)
                xg[i] = *(const float4*)(X + (size_t)(row0 + xr_ + 32*i) * HID + k0 + xc4);
            #pragma unroll
            for (int i = 0; i < 2; i++)
                wg[i] = *(const float4*)(W + (size_t)(k0 + wr_ + 16*i) * DIM + wc4);
        }
        const float* Xc = sm + (cur ? P_SM_X1 : P_SM_X0);
        const float* Wc = sm + (cur ? P_SM_W1 : P_SM_W0);
        const float* xa = Xc + (wrow + g) * XS_STR + t;
        const float* wb = Wc + t * WS_STR + g;

        #pragma unroll
        for (int kc = 0; kc < 4; kc++) {
            uint32_t a0 = __float_as_uint(xa[kc*8]);
            uint32_t a1 = __float_as_uint(xa[kc*8 + 8*XS_STR]);
            uint32_t a2 = __float_as_uint(xa[kc*8 + 4]);
            uint32_t a3 = __float_as_uint(xa[kc*8 + 4 + 8*XS_STR]);
            #pragma unroll
            for (int nt = 0; nt < 8; nt++) {
                uint32_t b0 = __float_as_uint(wb[(kc*8)    *WS_STR + nt*8]);
                uint32_t b1 = __float_as_uint(wb[(kc*8 + 4)*WS_STR + nt*8]);
                mma8(c[nt], a0, a1, a2, a3, b0, b1);
            }
        }
        if (s < 31) {
            float* xd = sm + (cur ? P_SM_X0 : P_SM_X1);
            float* wd = sm + (cur ? P_SM_W0 : P_SM_W1);
            #pragma unroll
            for (int i = 0; i < 4; i++)
                *(float4*)(xd + (xr_ + 32*i)*XS_STR + xc4) =
                    make_float4(tfv(xg[i].x), tfv(xg[i].y), tfv(xg[i].z), tfv(xg[i].w));
            #pragma unroll
            for (int i = 0; i < 2; i++)
                *(float4*)(wd + (wr_ + 16*i)*WS_STR + wc4) =
                    make_float4(tfv(wg[i].x), tfv(wg[i].y), tfv(wg[i].z), tfv(wg[i].w));
        }
        __syncthreads();
    }

    // epilogue: +bias, (q: *0.125), round to fp16
    const int r = row0 + wrow + g;
    uint32_t* Y32 = (uint32_t*)((blockIdx.z == 0) ? g_qh :
                                (blockIdx.z == 1) ? g_kh : g_vh);
    const float osc = (blockIdx.z == 0) ? 0.125f : 1.0f;
    #pragma unroll
    for (int nt = 0; nt < 8; nt++) {
        float2 b2 = *(const float2*)(bias + nt*8 + 2*t);
        Y32[(size_t)r       * 32 + nt*4 + t] = h2((c[nt][0] + b2.x)*osc, (c[nt][1] + b2.y)*osc);
        Y32[(size_t)(r + 8) * 32 + nt*4 + t] = h2((c[nt][2] + b2.x)*osc, (c[nt][3] + b2.y)*osc);
    }
}

// ---------------------------------------------------------------------------
// Flash attention, all-fp16 operands (fp32 accum). 64 Q-rows per CTA,
// 128 threads (4 warps x 16 rows). QK: fp16 m16n8k16, K B-fragments via
// non-trans ldmatrix.x4. PV: fp16, V via trans ldmatrix.x4. Q fragments
// hoisted to registers. cp.async double buffering, 1 barrier per tile.
// ---------------------------------------------------------------------------
#define HST 36                               // u32 words per fp16 row (64+8 pad halves)
#define SM_Q   0
#define SM_K0  (64*HST)                      // 2304
#define SM_K1  (SM_K0 + 64*HST)              // 4608
#define SM_V0  (SM_K1 + 64*HST)              // 6912
#define SM_V1  (SM_V0 + 64*HST)              // 9216
#define SM_MK0 (SM_V1 + 64*HST)              // 11520
#define SM_MK1 (SM_MK0 + 64)                 // 11584
#define ATTN_WORDS (SM_MK1 + 64)             // 11648
#define ATTN_SMEM_BYTES (ATTN_WORDS * 4)     // 46592

__global__ __launch_bounds__(128, 4) void attn_mma(
    const int* __restrict__ mask, float* __restrict__ out)
{
    extern __shared__ float sm[];
    uint32_t smb;
    asm("{ .reg .u64 tt; cvta.to.shared.u64 tt, %1; cvt.u32.u64 %0, tt; }"
        : "=r"(smb) : "l"(sm));

    const int tid  = threadIdx.x;
    const int warp = tid >> 5, lane = tid & 31;
    const int g = lane >> 2, t = lane & 3;
    const int wrow = warp * 16;

    const int b  = blockIdx.y;
    const int q0 = blockIdx.x * 64;
    const uint16_t* qb = g_qh + ((size_t)b * SEQ + q0) * DIM;
    const uint16_t* kb = g_kh + (size_t)b * SEQ * DIM;
    const uint16_t* vb = g_vh + (size_t)b * SEQ * DIM;
    const int*      mb = mask + (size_t)b * SEQ;

    // ---- prologue: stage Q + tile0 (K0/V0/MK0), one group ----
    #pragma unroll
    for (int i = 0; i < 4; i++) {
        const int c = tid + i*128;               // 512 chunks (64 rows x 8)
        const int row = c >> 3, w4 = (c & 7) << 2;
        cpa16(smb + 4u*(SM_Q + row*HST + w4), qb + (size_t)row*DIM + w4*2);
    }
    #pragma unroll
    for (int i = 0; i < 4; i++) {
        const int c = tid + i*128;
        const int key = c >> 3, w4 = (c & 7) << 2;
        cpa16(smb + 4u*(SM_K0 + key*HST + w4), kb + (size_t)key*DIM + w4*2);
    }
    #pragma unroll
    for (int i = 0; i < 4; i++) {
        const int c = tid + i*128;
        const int key = c >> 3, w4 = (c & 7) << 2;
        cpa16(smb + 4u*(SM_V0 + key*HST + w4), vb + (size_t)key*DIM + w4*2);
    }
    if (tid < 16)
        cpa16(smb + 4u*(SM_MK0 + tid*4), mb + tid*4);
    cpa_commit();
    cpa_wait0();
    __syncthreads();

    // ---- hoist Q fragments: 4 k-chunks, ldmatrix.x4 non-trans (A layout) ----
    // lane: mat = lane>>3, r = lane&7; row = wrow + ((mat&1)<<3) + r; col u32 = kc*8 + ((mat>>1)<<2)
    uint32_t qf[4][4];
    {
        const int mat = lane >> 3, r7 = lane & 7;
        const uint32_t qrow = smb + 4u*(SM_Q + (wrow + ((mat & 1) << 3) + r7) * HST
                                        + ((mat >> 1) << 2));
        #pragma unroll
        for (int kc = 0; kc < 4; kc++)
            ldsm_x4(qf[kc][0], qf[kc][1], qf[kc][2], qf[kc][3], qrow + 4u*(kc*8));
    }

    float o[8][4];
    #pragma unroll
    for (int nt = 0; nt < 8; nt++)
        #pragma unroll
        for (int j = 0; j < 4; j++) o[nt][j] = 0.f;
    float m0 = -1e30f, m1 = -1e30f, l0 = 0.f, l1 = 0.f;

    // K B-fragment lane mapping (non-trans): mat=lane>>3, r=lane&7
    //   key = n0 + ((mat>>1)<<3) + r ; col u32 = kc*8 + ((mat&1)<<2)
    const int kmat = lane >> 3, kr7 = lane & 7;
    const int kkey_off = ((kmat >> 1) << 3) + kr7;
    const int kcol_off = (kmat & 1) << 2;
    // V B-fragment lane mapping (trans, validated R3):
    const int vrow = (((lane >> 3) & 1) << 3) + (lane & 7);
    const int vcol4 = ((lane >> 3) >> 1) << 2;

    for (int kt = 0; kt < 64; kt++) {
        const int buf = kt & 1;
        cpa_wait0();
        __syncthreads();

        // stage tile kt+1 into other buffer
        if (kt < 63) {
            const int kbw = buf ? SM_K0 : SM_K1;
            const int vbw = buf ? SM_V0 : SM_V1;
            const int mbw = buf ? SM_MK0 : SM_MK1;
            const size_t kofs = (size_t)(kt + 1) * 64;
            #pragma unroll
            for (int i = 0; i < 4; i++) {
                const int c = tid + i*128;
                const int key = c >> 3, w4 = (c & 7) << 2;
                cpa16(smb + 4u*(kbw + key*HST + w4), kb + (kofs + key)*DIM + w4*2);
            }
            #pragma unroll
            for (int i = 0; i < 4; i++) {
                const int c = tid + i*128;
                const int key = c >> 3, w4 = (c & 7) << 2;
                cpa16(smb + 4u*(vbw + key*HST + w4), vb + (kofs + key)*DIM + w4*2);
            }
            if (tid < 16)
                cpa16(smb + 4u*(mbw + tid*4), mb + kofs + tid*4);
            cpa_commit();
        }

        const int*     Mc  = (const int*)sm + (buf ? SM_MK1 : SM_MK0);
        const uint32_t kba = smb + 4u*((buf ? SM_K1 : SM_K0) + kkey_off*HST + kcol_off);
        const uint32_t vba = smb + 4u*((buf ? SM_V1 : SM_V0) + vrow*HST + vcol4);

        // ---- S = Q @ K^T (fp16 inputs, fp32 accum) ----
        float c[8][4];
        #pragma unroll
        for (int nt = 0; nt < 8; nt++)
            #pragma unroll
            for (int j = 0; j < 4; j++) c[nt][j] = 0.f;

        #pragma unroll
        for (int kc = 0; kc < 4; kc++) {
            #pragma unroll
            for (int np = 0; np < 4; np++) {
                uint32_t b0, b1, b2, b3;
                ldsm_x4(b0, b1, b2, b3, kba + 4u*(np*16*HST + kc*8));
                mma16(c[2*np],     qf[kc][0], qf[kc][1], qf[kc][2], qf[kc][3], b0, b1);
                mma16(c[2*np + 1], qf[kc][0], qf[kc][1], qf[kc][2], qf[kc][3], b2, b3);
            }
        }

        // ---- mask + row max ----
        float mx0 = -1e30f, mx1 = -1e30f;
        #pragma unroll
        for (int nt = 0; nt < 8; nt++) {
            int2 mv = *(const int2*)(Mc + nt*8 + 2*t);
            if (mv.x == 0) { c[nt][0] = -1e9f; c[nt][2] = -1e9f; }
            if (mv.y == 0) { c[nt][1] = -1e9f; c[nt][3] = -1e9f; }
            mx0 = fmaxf(mx0, fmaxf(c[nt][0], c[nt][1]));
            mx1 = fmaxf(mx1, fmaxf(c[nt][2], c[nt][3]));
        }
        mx0 = fmaxf(mx0, __shfl_xor_sync(0xffffffffu, mx0, 1));
        mx0 = fmaxf(mx0, __shfl_xor_sync(0xffffffffu, mx0, 2));
        mx1 = fmaxf(mx1, __shfl_xor_sync(0xffffffffu, mx1, 1));
        mx1 = fmaxf(mx1, __shfl_xor_sync(0xffffffffu, mx1, 2));

        const float mn0 = fmaxf(m0, mx0), mn1 = fmaxf(m1, mx1);

        float s0 = 0.f, s1 = 0.f;
        #pragma unroll
        for (int nt = 0; nt < 8; nt++) {
            c[nt][0] = __expf(c[nt][0] - mn0);
            c[nt][1] = __expf(c[nt][1] - mn0);
            c[nt][2] = __expf(c[nt][2] - mn1);
            c[nt][3] = __expf(c[nt][3] - mn1);
            s0 += c[nt][0] + c[nt][1];
            s1 += c[nt][2] + c[nt][3];
        }
        s0 += __shfl_xor_sync(0xffffffffu, s0, 1);
        s0 += __shfl_xor_sync(0xffffffffu, s0, 2);
        s1 += __shfl_xor_sync(0xffffffffu, s1, 1);
        s1 += __shfl_xor_sync(0xffffffffu, s1, 2);

        const float co0 = __expf(m0 - mn0), co1 = __expf(m1 - mn1);
        m0 = mn0; m1 = mn1;
        l0 = l0 * co0 + s0;
        l1 = l1 * co1 + s1;

        #pragma unroll
        for (int nt = 0; nt < 8; nt++) {
            o[nt][0] *= co0; o[nt][1] *= co0;
            o[nt][2] *= co1; o[nt][3] *= co1;
        }

        // ---- O += P @ V : P fragments built directly from accumulators ----
        #pragma unroll
        for (int kc = 0; kc < 4; kc++) {
            uint32_t a0 = h2(c[2*kc][0],   c[2*kc][1]);
            uint32_t a1 = h2(c[2*kc][2],   c[2*kc][3]);
            uint32_t a2 = h2(c[2*kc+1][0], c[2*kc+1][1]);
            uint32_t a3 = h2(c[2*kc+1][2], c[2*kc+1][3]);
            #pragma unroll
            for (int ntp = 0; ntp < 4; ntp++) {
                uint32_t b0, b1, b2, b3;
                ldsm_x4_t(b0, b1, b2, b3, vba + 4u*(kc*16*HST + ntp*8));
                mma16(o[2*ntp],     a0, a1, a2, a3, b0, b1);
                mma16(o[2*ntp + 1], a0, a1, a2, a3, b2, b3);
            }
        }
    }

    // ---- epilogue: normalize + store ----
    const float i0 = 1.f / l0, i1 = 1.f / l1;
    float* ob = out + ((size_t)b * SEQ + q0 + wrow + g) * DIM + 2*t;
    #pragma unroll
    for (int nt = 0; nt < 8; nt++) {
        *(float2*)(ob + nt*8)         = make_float2(o[nt][0]*i0, o[nt][1]*i0);
        *(float2*)(ob + nt*8 + 8*DIM) = make_float2(o[nt][2]*i1, o[nt][3]*i1);
    }
}

// ---------------------------------------------------------------------------
extern "C" void kernel_launch(void* const* d_in, const int* in_sizes, int n_in,
                              void* d_out, int out_size)
{
    const float* query = (const float*)d_in[0];
    const float* key_  = (const float*)d_in[1];
    const float* value = (const float*)d_in[2];
    const int*   mask  = (const int*)d_in[3];
    const float* Wq = (const float*)d_in[4];
    const float* bq = (const float*)d_in[5];
    const float* Wk = (const float*)d_in[6];
    const float* bk = (const float*)d_in[7];
    const float* Wv = (const float*)d_in[8];
    const float* bv = (const float*)d_in[9];
    float* out = (float*)d_out;

    cudaFuncSetAttribute(proj_mma, cudaFuncAttributeMaxDynamicSharedMemorySize,
                         PROJ_SMEM_BYTES);
    cudaFuncSetAttribute(attn_mma, cudaFuncAttributeMaxDynamicSharedMemorySize,
                         ATTN_SMEM_BYTES);

    dim3 gp(M_TOT / 128, 1, 3);
    proj_mma<<<gp, 256, PROJ_SMEM_BYTES>>>(query, key_, value,
                                           Wq, bq, Wk, bk, Wv, bv);

    dim3 ga(SEQ / 64, BATCH);
    attn_mma<<<ga, 128, ATTN_SMEM_BYTES>>>(mask, out);
}

// round 7
// speedup vs baseline: 5.8025x; 1.1186x over previous
#include <cuda_runtime.h>
#include <stdint.h>

// Problem: B=4, S=4096, H=1024, D=64
#define BATCH 4
#define SEQ   4096
#define SEQH  2048          // per split-K half
#define HID   1024
#define DIM   64
#define M_TOT (BATCH*SEQ)   // 16384

// Scratch: projected q (pre-scaled 1/8), k, v — all fp16
__device__ uint16_t g_qh[M_TOT * DIM];
__device__ uint16_t g_kh[M_TOT * DIM];
__device__ uint16_t g_vh[M_TOT * DIM];
// Split-K partials
__device__ float g_po[2][M_TOT * DIM];
__device__ float g_pm[2][M_TOT];
__device__ float g_pl[2][M_TOT];

// ---------------------------------------------------------------------------
// helpers
// ---------------------------------------------------------------------------
__device__ __forceinline__ uint32_t h2(float lo, float hi) {
    uint32_t u;
    asm("cvt.rn.f16x2.f32 %0, %1, %2;" : "=r"(u) : "f"(hi), "f"(lo));
    return u;
}

__device__ __forceinline__ void mma16(float* c,
                                      uint32_t a0, uint32_t a1, uint32_t a2, uint32_t a3,
                                      uint32_t b0, uint32_t b1) {
    asm volatile(
        "mma.sync.aligned.m16n8k16.row.col.f32.f16.f16.f32 "
        "{%0,%1,%2,%3},{%4,%5,%6,%7},{%8,%9},{%0,%1,%2,%3};"
        : "+f"(c[0]), "+f"(c[1]), "+f"(c[2]), "+f"(c[3])
        : "r"(a0), "r"(a1), "r"(a2), "r"(a3), "r"(b0), "r"(b1));
}

__device__ __forceinline__ void ldsm_x4(uint32_t& r0, uint32_t& r1,
                                        uint32_t& r2, uint32_t& r3, uint32_t saddr) {
    asm volatile(
        "ldmatrix.sync.aligned.m8n8.x4.shared.b16 {%0,%1,%2,%3}, [%4];"
        : "=r"(r0), "=r"(r1), "=r"(r2), "=r"(r3) : "r"(saddr));
}

__device__ __forceinline__ void ldsm_x4_t(uint32_t& r0, uint32_t& r1,
                                          uint32_t& r2, uint32_t& r3, uint32_t saddr) {
    asm volatile(
        "ldmatrix.sync.aligned.m8n8.x4.trans.shared.b16 {%0,%1,%2,%3}, [%4];"
        : "=r"(r0), "=r"(r1), "=r"(r2), "=r"(r3) : "r"(saddr));
}

__device__ __forceinline__ void cpa16(uint32_t saddr, const void* gaddr) {
    asm volatile("cp.async.ca.shared.global [%0], [%1], 16;"
                 :: "r"(saddr), "l"(gaddr) : "memory");
}
__device__ __forceinline__ void cpa_commit() {
    asm volatile("cp.async.commit_group;" ::: "memory");
}
__device__ __forceinline__ void cpa_wait0() {
    asm volatile("cp.async.wait_group 0;" ::: "memory");
}

// ---------------------------------------------------------------------------
// Projection GEMM, all-fp16 operands (fp32 accum): Y[M,64] = X[M,1024]@W + b
// X/W rounded to fp16 in registers, staged to smem, fragments via ldmatrix.
// Epilogue rounds to fp16: z=0 -> g_qh (*0.125), z=1 -> g_kh, z=2 -> g_vh
// ---------------------------------------------------------------------------
#define PXST 20   // u32 words per X row (32 halves + 8 pad)
#define PWST 36   // u32 words per W row (64 halves + 8 pad)
#define PX0 0
#define PX1 (128*PXST)            // 2560
#define PW0 (2*128*PXST)          // 5120
#define PW1 (PW0 + 32*PWST)       // 6272
#define PROJ_WORDS (PW1 + 32*PWST)            // 7424
#define PROJ_SMEM_BYTES (PROJ_WORDS * 4)      // 29696

__global__ __launch_bounds__(256, 2) void proj_mma(
    const float* __restrict__ Xq, const float* __restrict__ Xk, const float* __restrict__ Xv,
    const float* __restrict__ Wq, const float* __restrict__ bq,
    const float* __restrict__ Wk, const float* __restrict__ bk,
    const float* __restrict__ Wv, const float* __restrict__ bv)
{
    const float* X; const float* W; const float* bias;
    if (blockIdx.z == 0)      { X = Xq; W = Wq; bias = bq; }
    else if (blockIdx.z == 1) { X = Xk; W = Wk; bias = bk; }
    else                      { X = Xv; W = Wv; bias = bv; }

    extern __shared__ float sm[];
    uint32_t* smw = (uint32_t*)sm;
    uint32_t smb;
    asm("{ .reg .u64 tt; cvta.to.shared.u64 tt, %1; cvt.u32.u64 %0, tt; }"
        : "=r"(smb) : "l"(sm));

    const int tid  = threadIdx.x;
    const int warp = tid >> 5, lane = tid & 31;
    const int g = lane >> 2, t = lane & 3;
    const int wrow = warp * 16;
    const int row0 = blockIdx.x * 128;

    // staging mapping
    const int xrow = tid >> 3,  xc4 = (tid & 7) << 2;    // X: +128 rows per iter? no: c=tid+i*256
    const int wrow_s = tid >> 4, wc4 = (tid & 15) << 2;  // W: c=tid+i*256
    (void)xrow; (void)xc4; (void)wrow_s; (void)wc4;

    float4 xg[4], wg[2];

    // fetch step 0
    #pragma unroll
    for (int i = 0; i < 4; i++) {
        const int c = tid + i*256, row = c >> 3, c4 = (c & 7) << 2;
        xg[i] = *(const float4*)(X + (size_t)(row0 + row) * HID + c4);
    }
    #pragma unroll
    for (int i = 0; i < 2; i++) {
        const int c = tid + i*256, row = c >> 4, c4 = (c & 15) << 2;
        wg[i] = *(const float4*)(W + (size_t)row * DIM + c4);
    }
    // store step 0 -> buffer 0
    {
        uint32_t* Xd = smw + PX0;
        uint32_t* Wd = smw + PW0;
        #pragma unroll
        for (int i = 0; i < 4; i++) {
            const int c = tid + i*256, row = c >> 3, c4 = (c & 7) << 2;
            uint32_t* p = Xd + row*PXST + (c4 >> 1);
            p[0] = h2(xg[i].x, xg[i].y); p[1] = h2(xg[i].z, xg[i].w);
        }
        #pragma unroll
        for (int i = 0; i < 2; i++) {
            const int c = tid + i*256, row = c >> 4, c4 = (c & 15) << 2;
            uint32_t* p = Wd + row*PWST + (c4 >> 1);
            p[0] = h2(wg[i].x, wg[i].y); p[1] = h2(wg[i].z, wg[i].w);
        }
    }
    __syncthreads();

    float c[8][4];
    #pragma unroll
    for (int nt = 0; nt < 8; nt++)
        #pragma unroll
        for (int j = 0; j < 4; j++) c[nt][j] = 0.f;

    // fragment lane mappings (validated in attention kernel)
    const int amat = lane >> 3, r7 = lane & 7;
    const int arow_off = ((amat & 1) << 3) + r7;       // A (non-trans)
    const int acol_off = (amat >> 1) << 2;
    const int brow = ((amat & 1) << 3) + r7;           // B (trans)
    const int bcol4 = (amat >> 1) << 2;

    for (int s = 0; s < 32; s++) {
        const int cur = s & 1;
        if (s < 31) {
            const int k0 = (s + 1) * 32;
            #pragma unroll
            for (int i = 0; i < 4; i++) {
                const int cc = tid + i*256, row = cc >> 3, c4 = (cc & 7) << 2;
                xg[i] = *(const float4*)(X + (size_t)(row0 + row) * HID + k0 + c4);
            }
            #pragma unroll
            for (int i = 0; i < 2; i++) {
                const int cc = tid + i*256, row = cc >> 4, c4 = (cc & 15) << 2;
                wg[i] = *(const float4*)(W + (size_t)(k0 + row) * DIM + c4);
            }
        }
        const uint32_t a_base = smb + 4u*((cur ? PX1 : PX0)
                                          + (wrow + arow_off)*PXST + acol_off);
        const uint32_t b_base = smb + 4u*((cur ? PW1 : PW0) + brow*PWST + bcol4);

        #pragma unroll
        for (int kc = 0; kc < 2; kc++) {
            uint32_t a0, a1, a2, a3;
            ldsm_x4(a0, a1, a2, a3, a_base + 4u*(kc*8));
            #pragma unroll
            for (int ntp = 0; ntp < 4; ntp++) {
                uint32_t b0, b1, b2, b3;
                ldsm_x4_t(b0, b1, b2, b3, b_base + 4u*(kc*16*PWST + ntp*8));
                mma16(c[2*ntp],     a0, a1, a2, a3, b0, b1);
                mma16(c[2*ntp + 1], a0, a1, a2, a3, b2, b3);
            }
        }

        if (s < 31) {
            uint32_t* Xd = smw + (cur ? PX0 : PX1);
            uint32_t* Wd = smw + (cur ? PW0 : PW1);
            #pragma unroll
            for (int i = 0; i < 4; i++) {
                const int cc = tid + i*256, row = cc >> 3, c4 = (cc & 7) << 2;
                uint32_t* p = Xd + row*PXST + (c4 >> 1);
                p[0] = h2(xg[i].x, xg[i].y); p[1] = h2(xg[i].z, xg[i].w);
            }
            #pragma unroll
            for (int i = 0; i < 2; i++) {
                const int cc = tid + i*256, row = cc >> 4, c4 = (cc & 15) << 2;
                uint32_t* p = Wd + row*PWST + (c4 >> 1);
                p[0] = h2(wg[i].x, wg[i].y); p[1] = h2(wg[i].z, wg[i].w);
            }
        }
        __syncthreads();
    }

    // epilogue: +bias, (q: *0.125), round to fp16
    const int r = row0 + wrow + g;
    uint32_t* Y32 = (uint32_t*)((blockIdx.z == 0) ? g_qh :
                                (blockIdx.z == 1) ? g_kh : g_vh);
    const float osc = (blockIdx.z == 0) ? 0.125f : 1.0f;
    #pragma unroll
    for (int nt = 0; nt < 8; nt++) {
        float2 b2 = *(const float2*)(bias + nt*8 + 2*t);
        Y32[(size_t)r       * 32 + nt*4 + t] = h2((c[nt][0] + b2.x)*osc, (c[nt][1] + b2.y)*osc);
        Y32[(size_t)(r + 8) * 32 + nt*4 + t] = h2((c[nt][2] + b2.x)*osc, (c[nt][3] + b2.y)*osc);
    }
}

// ---------------------------------------------------------------------------
// Flash attention, split-K (z = KV half). Per CTA: 64 Q rows, 128 threads,
// 2048 keys (32 tiles). Writes unnormalized partial O + (m,l) per row.
// ---------------------------------------------------------------------------
#define HST 36                               // u32 words per fp16 row
#define SM_Q   0
#define SM_K0  (64*HST)
#define SM_K1  (SM_K0 + 64*HST)
#define SM_V0  (SM_K1 + 64*HST)
#define SM_V1  (SM_V0 + 64*HST)
#define SM_MK0 (SM_V1 + 64*HST)
#define SM_MK1 (SM_MK0 + 64)
#define ATTN_WORDS (SM_MK1 + 64)
#define ATTN_SMEM_BYTES (ATTN_WORDS * 4)     // 46592

__global__ __launch_bounds__(128, 4) void attn_mma(const int* __restrict__ mask)
{
    extern __shared__ float sm[];
    uint32_t smb;
    asm("{ .reg .u64 tt; cvta.to.shared.u64 tt, %1; cvt.u32.u64 %0, tt; }"
        : "=r"(smb) : "l"(sm));

    const int tid  = threadIdx.x;
    const int warp = tid >> 5, lane = tid & 31;
    const int g = lane >> 2, t = lane & 3;
    const int wrow = warp * 16;

    const int b  = blockIdx.y;
    const int z  = blockIdx.z;
    const int q0 = blockIdx.x * 64;
    const uint16_t* qb = g_qh + ((size_t)b * SEQ + q0) * DIM;
    const uint16_t* kb = g_kh + ((size_t)b * SEQ + z * SEQH) * DIM;
    const uint16_t* vb = g_vh + ((size_t)b * SEQ + z * SEQH) * DIM;
    const int*      mb = mask + (size_t)b * SEQ + z * SEQH;

    // ---- prologue: stage Q + tile0 ----
    #pragma unroll
    for (int i = 0; i < 4; i++) {
        const int c = tid + i*128;
        const int row = c >> 3, w4 = (c & 7) << 2;
        cpa16(smb + 4u*(SM_Q + row*HST + w4), qb + (size_t)row*DIM + w4*2);
    }
    #pragma unroll
    for (int i = 0; i < 4; i++) {
        const int c = tid + i*128;
        const int key = c >> 3, w4 = (c & 7) << 2;
        cpa16(smb + 4u*(SM_K0 + key*HST + w4), kb + (size_t)key*DIM + w4*2);
    }
    #pragma unroll
    for (int i = 0; i < 4; i++) {
        const int c = tid + i*128;
        const int key = c >> 3, w4 = (c & 7) << 2;
        cpa16(smb + 4u*(SM_V0 + key*HST + w4), vb + (size_t)key*DIM + w4*2);
    }
    if (tid < 16)
        cpa16(smb + 4u*(SM_MK0 + tid*4), mb + tid*4);
    cpa_commit();
    cpa_wait0();
    __syncthreads();

    // ---- hoist Q fragments ----
    uint32_t qf[4][4];
    {
        const int mat = lane >> 3, r7 = lane & 7;
        const uint32_t qrow = smb + 4u*(SM_Q + (wrow + ((mat & 1) << 3) + r7) * HST
                                        + ((mat >> 1) << 2));
        #pragma unroll
        for (int kc = 0; kc < 4; kc++)
            ldsm_x4(qf[kc][0], qf[kc][1], qf[kc][2], qf[kc][3], qrow + 4u*(kc*8));
    }

    float o[8][4];
    #pragma unroll
    for (int nt = 0; nt < 8; nt++)
        #pragma unroll
        for (int j = 0; j < 4; j++) o[nt][j] = 0.f;
    float m0 = -1e30f, m1 = -1e30f, l0 = 0.f, l1 = 0.f;

    const int kmat = lane >> 3, kr7 = lane & 7;
    const int kkey_off = ((kmat >> 1) << 3) + kr7;
    const int kcol_off = (kmat & 1) << 2;
    const int vrow = (((lane >> 3) & 1) << 3) + (lane & 7);
    const int vcol4 = ((lane >> 3) >> 1) << 2;

    for (int kt = 0; kt < 32; kt++) {
        const int buf = kt & 1;
        cpa_wait0();
        __syncthreads();

        if (kt < 31) {
            const int kbw = buf ? SM_K0 : SM_K1;
            const int vbw = buf ? SM_V0 : SM_V1;
            const int mbw = buf ? SM_MK0 : SM_MK1;
            const size_t kofs = (size_t)(kt + 1) * 64;
            #pragma unroll
            for (int i = 0; i < 4; i++) {
                const int c = tid + i*128;
                const int key = c >> 3, w4 = (c & 7) << 2;
                cpa16(smb + 4u*(kbw + key*HST + w4), kb + (kofs + key)*DIM + w4*2);
            }
            #pragma unroll
            for (int i = 0; i < 4; i++) {
                const int c = tid + i*128;
                const int key = c >> 3, w4 = (c & 7) << 2;
                cpa16(smb + 4u*(vbw + key*HST + w4), vb + (kofs + key)*DIM + w4*2);
            }
            if (tid < 16)
                cpa16(smb + 4u*(mbw + tid*4), mb + kofs + tid*4);
            cpa_commit();
        }

        const int*     Mc  = (const int*)sm + (buf ? SM_MK1 : SM_MK0);
        const uint32_t kba = smb + 4u*((buf ? SM_K1 : SM_K0) + kkey_off*HST + kcol_off);
        const uint32_t vba = smb + 4u*((buf ? SM_V1 : SM_V0) + vrow*HST + vcol4);

        // ---- S = Q @ K^T ----
        float c[8][4];
        #pragma unroll
        for (int nt = 0; nt < 8; nt++)
            #pragma unroll
            for (int j = 0; j < 4; j++) c[nt][j] = 0.f;

        #pragma unroll
        for (int kc = 0; kc < 4; kc++) {
            #pragma unroll
            for (int np = 0; np < 4; np++) {
                uint32_t b0, b1, b2, b3;
                ldsm_x4(b0, b1, b2, b3, kba + 4u*(np*16*HST + kc*8));
                mma16(c[2*np],     qf[kc][0], qf[kc][1], qf[kc][2], qf[kc][3], b0, b1);
                mma16(c[2*np + 1], qf[kc][0], qf[kc][1], qf[kc][2], qf[kc][3], b2, b3);
            }
        }

        // ---- mask + row max ----
        float mx0 = -1e30f, mx1 = -1e30f;
        #pragma unroll
        for (int nt = 0; nt < 8; nt++) {
            int2 mv = *(const int2*)(Mc + nt*8 + 2*t);
            if (mv.x == 0) { c[nt][0] = -1e9f; c[nt][2] = -1e9f; }
            if (mv.y == 0) { c[nt][1] = -1e9f; c[nt][3] = -1e9f; }
            mx0 = fmaxf(mx0, fmaxf(c[nt][0], c[nt][1]));
            mx1 = fmaxf(mx1, fmaxf(c[nt][2], c[nt][3]));
        }
        mx0 = fmaxf(mx0, __shfl_xor_sync(0xffffffffu, mx0, 1));
        mx0 = fmaxf(mx0, __shfl_xor_sync(0xffffffffu, mx0, 2));
        mx1 = fmaxf(mx1, __shfl_xor_sync(0xffffffffu, mx1, 1));
        mx1 = fmaxf(mx1, __shfl_xor_sync(0xffffffffu, mx1, 2));

        const float mn0 = fmaxf(m0, mx0), mn1 = fmaxf(m1, mx1);

        float s0 = 0.f, s1 = 0.f;
        #pragma unroll
        for (int nt = 0; nt < 8; nt++) {
            c[nt][0] = __expf(c[nt][0] - mn0);
            c[nt][1] = __expf(c[nt][1] - mn0);
            c[nt][2] = __expf(c[nt][2] - mn1);
            c[nt][3] = __expf(c[nt][3] - mn1);
            s0 += c[nt][0] + c[nt][1];
            s1 += c[nt][2] + c[nt][3];
        }
        s0 += __shfl_xor_sync(0xffffffffu, s0, 1);
        s0 += __shfl_xor_sync(0xffffffffu, s0, 2);
        s1 += __shfl_xor_sync(0xffffffffu, s1, 1);
        s1 += __shfl_xor_sync(0xffffffffu, s1, 2);

        const float co0 = __expf(m0 - mn0), co1 = __expf(m1 - mn1);
        m0 = mn0; m1 = mn1;
        l0 = l0 * co0 + s0;
        l1 = l1 * co1 + s1;

        #pragma unroll
        for (int nt = 0; nt < 8; nt++) {
            o[nt][0] *= co0; o[nt][1] *= co0;
            o[nt][2] *= co1; o[nt][3] *= co1;
        }

        // ---- O += P @ V ----
        #pragma unroll
        for (int kc = 0; kc < 4; kc++) {
            uint32_t a0 = h2(c[2*kc][0],   c[2*kc][1]);
            uint32_t a1 = h2(c[2*kc][2],   c[2*kc][3]);
            uint32_t a2 = h2(c[2*kc+1][0], c[2*kc+1][1]);
            uint32_t a3 = h2(c[2*kc+1][2], c[2*kc+1][3]);
            #pragma unroll
            for (int ntp = 0; ntp < 4; ntp++) {
                uint32_t b0, b1, b2, b3;
                ldsm_x4_t(b0, b1, b2, b3, vba + 4u*(kc*16*HST + ntp*8));
                mma16(o[2*ntp],     a0, a1, a2, a3, b0, b1);
                mma16(o[2*ntp + 1], a0, a1, a2, a3, b2, b3);
            }
        }
    }

    // ---- epilogue: write unnormalized partial O + (m,l) ----
    const int ridx = b * SEQ + q0 + wrow + g;
    float* pob = g_po[z] + (size_t)ridx * DIM + 2*t;
    #pragma unroll
    for (int nt = 0; nt < 8; nt++) {
        *(float2*)(pob + nt*8)         = make_float2(o[nt][0], o[nt][1]);
        *(float2*)(pob + nt*8 + 8*DIM) = make_float2(o[nt][2], o[nt][3]);
    }
    if (t == 0) {
        g_pm[z][ridx]     = m0;  g_pl[z][ridx]     = l0;
        g_pm[z][ridx + 8] = m1;  g_pl[z][ridx + 8] = l1;
    }
}

// ---------------------------------------------------------------------------
// Merge: out = (o0*c0 + o1*c1) / (l0*c0 + l1*c1), c_i = exp(m_i - max(m))
// ---------------------------------------------------------------------------
__global__ __launch_bounds__(256) void merge_k(float* __restrict__ out)
{
    const int e = blockIdx.x * 256 + threadIdx.x;   // float4 index
    const int row = e >> 4;                         // 16 float4 per row
    const float m0 = g_pm[0][row], m1 = g_pm[1][row];
    const float l0 = g_pl[0][row], l1 = g_pl[1][row];
    const float m = fmaxf(m0, m1);
    const float c0 = __expf(m0 - m), c1 = __expf(m1 - m);
    const float inv = 1.f / (l0*c0 + l1*c1);
    float4 a = ((const float4*)g_po[0])[e];
    float4 b = ((const float4*)g_po[1])[e];
    ((float4*)out)[e] = make_float4((a.x*c0 + b.x*c1) * inv,
                                    (a.y*c0 + b.y*c1) * inv,
                                    (a.z*c0 + b.z*c1) * inv,
                                    (a.w*c0 + b.w*c1) * inv);
}

// ---------------------------------------------------------------------------
extern "C" void kernel_launch(void* const* d_in, const int* in_sizes, int n_in,
                              void* d_out, int out_size)
{
    const float* query = (const float*)d_in[0];
    const float* key_  = (const float*)d_in[1];
    const float* value = (const float*)d_in[2];
    const int*   mask  = (const int*)d_in[3];
    const float* Wq = (const float*)d_in[4];
    const float* bq = (const float*)d_in[5];
    const float* Wk = (const float*)d_in[6];
    const float* bk = (const float*)d_in[7];
    const float* Wv = (const float*)d_in[8];
    const float* bv = (const float*)d_in[9];
    float* out = (float*)d_out;

    cudaFuncSetAttribute(proj_mma, cudaFuncAttributeMaxDynamicSharedMemorySize,
                         PROJ_SMEM_BYTES);
    cudaFuncSetAttribute(attn_mma, cudaFuncAttributeMaxDynamicSharedMemorySize,
                         ATTN_SMEM_BYTES);

    dim3 gp(M_TOT / 128, 1, 3);
    proj_mma<<<gp, 256, PROJ_SMEM_BYTES>>>(query, key_, value,
                                           Wq, bq, Wk, bk, Wv, bv);

    dim3 ga(SEQ / 64, BATCH, 2);
    attn_mma<<<ga, 128, ATTN_SMEM_BYTES>>>(mask);

    merge_k<<<(M_TOT * DIM / 4) / 256, 256>>>(out);
}

// round 8
// speedup vs baseline: 6.2866x; 1.0834x over previous
#include <cuda_runtime.h>
#include <stdint.h>

// Problem: B=4, S=4096, H=1024, D=64
#define BATCH 4
#define SEQ   4096
#define NSPL  4
#define SEQH  (SEQ/NSPL)    // 1024 keys per split
#define HID   1024
#define DIM   64
#define M_TOT (BATCH*SEQ)   // 16384

// Scratch: projected q (pre-scaled 1/8), k, v — all fp16
__device__ uint16_t g_qh[M_TOT * DIM];
__device__ uint16_t g_kh[M_TOT * DIM];
__device__ uint16_t g_vh[M_TOT * DIM];
// Split-K partials
__device__ float g_po[NSPL][M_TOT * DIM];
__device__ float g_pm[NSPL][M_TOT];
__device__ float g_pl[NSPL][M_TOT];

// ---------------------------------------------------------------------------
// helpers
// ---------------------------------------------------------------------------
__device__ __forceinline__ uint32_t f2tf_u(float x) {
    uint32_t u;
    asm("cvt.rna.tf32.f32 %0, %1;" : "=r"(u) : "f"(x));
    return u;
}

__device__ __forceinline__ uint32_t h2(float lo, float hi) {
    uint32_t u;
    asm("cvt.rn.f16x2.f32 %0, %1, %2;" : "=r"(u) : "f"(hi), "f"(lo));
    return u;
}

__device__ __forceinline__ void mma8(float* c,
                                     uint32_t a0, uint32_t a1, uint32_t a2, uint32_t a3,
                                     uint32_t b0, uint32_t b1) {
    asm volatile(
        "mma.sync.aligned.m16n8k8.row.col.f32.tf32.tf32.f32 "
        "{%0,%1,%2,%3},{%4,%5,%6,%7},{%8,%9},{%0,%1,%2,%3};"
        : "+f"(c[0]), "+f"(c[1]), "+f"(c[2]), "+f"(c[3])
        : "r"(a0), "r"(a1), "r"(a2), "r"(a3), "r"(b0), "r"(b1));
}

__device__ __forceinline__ void mma16(float* c,
                                      uint32_t a0, uint32_t a1, uint32_t a2, uint32_t a3,
                                      uint32_t b0, uint32_t b1) {
    asm volatile(
        "mma.sync.aligned.m16n8k16.row.col.f32.f16.f16.f32 "
        "{%0,%1,%2,%3},{%4,%5,%6,%7},{%8,%9},{%0,%1,%2,%3};"
        : "+f"(c[0]), "+f"(c[1]), "+f"(c[2]), "+f"(c[3])
        : "r"(a0), "r"(a1), "r"(a2), "r"(a3), "r"(b0), "r"(b1));
}

__device__ __forceinline__ void ldsm_x4(uint32_t& r0, uint32_t& r1,
                                        uint32_t& r2, uint32_t& r3, uint32_t saddr) {
    asm volatile(
        "ldmatrix.sync.aligned.m8n8.x4.shared.b16 {%0,%1,%2,%3}, [%4];"
        : "=r"(r0), "=r"(r1), "=r"(r2), "=r"(r3) : "r"(saddr));
}

__device__ __forceinline__ void ldsm_x4_t(uint32_t& r0, uint32_t& r1,
                                          uint32_t& r2, uint32_t& r3, uint32_t saddr) {
    asm volatile(
        "ldmatrix.sync.aligned.m8n8.x4.trans.shared.b16 {%0,%1,%2,%3}, [%4];"
        : "=r"(r0), "=r"(r1), "=r"(r2), "=r"(r3) : "r"(saddr));
}

__device__ __forceinline__ void cpa16(uint32_t saddr, const void* gaddr) {
    asm volatile("cp.async.ca.shared.global [%0], [%1], 16;"
                 :: "r"(saddr), "l"(gaddr) : "memory");
}
__device__ __forceinline__ void cpa_commit() {
    asm volatile("cp.async.commit_group;" ::: "memory");
}
__device__ __forceinline__ void cpa_wait0() {
    asm volatile("cp.async.wait_group 0;" ::: "memory");
}
__device__ __forceinline__ void cpa_wait1() {
    asm volatile("cp.async.wait_group 1;" ::: "memory");
}

// ---------------------------------------------------------------------------
// Projection GEMM: Y[M,64] = X[M,1024] @ W[1024,64] + b.
// Raw fp32 staged via cp.async (3-stage ring, depth-2 lookahead); fragments
// rounded to tf32 (cvt.rna) at load; tf32 mma, fp32 accum; fp16 outputs.
// z=0 -> g_qh (*0.125), z=1 -> g_kh, z=2 -> g_vh.
// ---------------------------------------------------------------------------
#define XS_STR 36
#define WS_STR 72
#define STG_FL (128*XS_STR + 32*WS_STR)     // 6912 floats per stage
#define PROJ_SMEM_BYTES (3 * STG_FL * 4)    // 82944

__global__ __launch_bounds__(256, 2) void proj_mma(
    const float* __restrict__ Xq, const float* __restrict__ Xk, const float* __restrict__ Xv,
    const float* __restrict__ Wq, const float* __restrict__ bq,
    const float* __restrict__ Wk, const float* __restrict__ bk,
    const float* __restrict__ Wv, const float* __restrict__ bv)
{
    const float* X; const float* W; const float* bias;
    if (blockIdx.z == 0)      { X = Xq; W = Wq; bias = bq; }
    else if (blockIdx.z == 1) { X = Xk; W = Wk; bias = bk; }
    else                      { X = Xv; W = Wv; bias = bv; }

    extern __shared__ float sm[];
    uint32_t smb;
    asm("{ .reg .u64 tt; cvta.to.shared.u64 tt, %1; cvt.u32.u64 %0, tt; }"
        : "=r"(smb) : "l"(sm));

    const int tid  = threadIdx.x;
    const int warp = tid >> 5, lane = tid & 31;
    const int g = lane >> 2, t = lane & 3;
    const int wrow = warp * 16;
    const int row0 = blockIdx.x * 128;

    // staging lambdas (stage s -> buffer bf)
    const int xrow = (tid + 0) >> 3;    // recomputed per chunk below
    (void)xrow;

    auto stage_issue = [&](int s, int bf) {
        const uint32_t base = smb + 4u * (bf * STG_FL);
        #pragma unroll
        for (int i = 0; i < 4; i++) {               // X: 128 rows x 8 chunks
            const int c = tid + i * 256;
            const int row = c >> 3, c4 = (c & 7) << 2;
            cpa16(base + 4u * (row * XS_STR + c4),
                  X + (size_t)(row0 + row) * HID + s * 32 + c4);
        }
        #pragma unroll
        for (int i = 0; i < 2; i++) {               // W: 32 rows x 16 chunks
            const int c = tid + i * 256;
            const int row = c >> 4, c4 = (c & 15) << 2;
            cpa16(base + 4u * (128 * XS_STR + row * WS_STR + c4),
                  W + (size_t)(s * 32 + row) * DIM + c4);
        }
        cpa_commit();
    };

    stage_issue(0, 0);
    stage_issue(1, 1);

    float c[8][4];
    #pragma unroll
    for (int nt = 0; nt < 8; nt++)
        #pragma unroll
        for (int j = 0; j < 4; j++) c[nt][j] = 0.f;

    int buf = 0;
    for (int s = 0; s < 32; s++) {
        cpa_wait1();          // stage s complete (<=1 younger group pending)
        __syncthreads();

        // issue stage s+2 into buffer (buf+2)%3 (or empty commit at tail)
        if (s + 2 < 32) {
            int nb = buf + 2; if (nb >= 3) nb -= 3;
            stage_issue(s + 2, nb);
        } else {
            cpa_commit();     // empty group keeps wait_group counting aligned
        }

        const float* Xc = sm + buf * STG_FL;
        const float* Wc = Xc + 128 * XS_STR;
        const float* xa = Xc + (wrow + g) * XS_STR + t;
        const float* wb = Wc + t * WS_STR + g;

        #pragma unroll
        for (int kc = 0; kc < 4; kc++) {
            uint32_t a0 = f2tf_u(xa[kc*8]);
            uint32_t a1 = f2tf_u(xa[kc*8 + 8*XS_STR]);
            uint32_t a2 = f2tf_u(xa[kc*8 + 4]);
            uint32_t a3 = f2tf_u(xa[kc*8 + 4 + 8*XS_STR]);
            #pragma unroll
            for (int nt = 0; nt < 8; nt++) {
                uint32_t b0 = f2tf_u(wb[(kc*8)    *WS_STR + nt*8]);
                uint32_t b1 = f2tf_u(wb[(kc*8 + 4)*WS_STR + nt*8]);
                mma8(c[nt], a0, a1, a2, a3, b0, b1);
            }
        }

        if (++buf == 3) buf = 0;
    }

    // epilogue: +bias, (q: *0.125), round to fp16
    const int r = row0 + wrow + g;
    uint32_t* Y32 = (uint32_t*)((blockIdx.z == 0) ? g_qh :
                                (blockIdx.z == 1) ? g_kh : g_vh);
    const float osc = (blockIdx.z == 0) ? 0.125f : 1.0f;
    #pragma unroll
    for (int nt = 0; nt < 8; nt++) {
        float2 b2 = *(const float2*)(bias + nt*8 + 2*t);
        Y32[(size_t)r       * 32 + nt*4 + t] = h2((c[nt][0] + b2.x)*osc, (c[nt][1] + b2.y)*osc);
        Y32[(size_t)(r + 8) * 32 + nt*4 + t] = h2((c[nt][2] + b2.x)*osc, (c[nt][3] + b2.y)*osc);
    }
}

// ---------------------------------------------------------------------------
// Flash attention, 4-way split-K (z = split). Per CTA: 64 Q rows, 128 threads,
// 1024 keys (16 tiles). Writes unnormalized partial O + (m,l) per row.
// ---------------------------------------------------------------------------
#define HST 36                               // u32 words per fp16 row
#define SM_Q   0
#define SM_K0  (64*HST)
#define SM_K1  (SM_K0 + 64*HST)
#define SM_V0  (SM_K1 + 64*HST)
#define SM_V1  (SM_V0 + 64*HST)
#define SM_MK0 (SM_V1 + 64*HST)
#define SM_MK1 (SM_MK0 + 64)
#define ATTN_WORDS (SM_MK1 + 64)
#define ATTN_SMEM_BYTES (ATTN_WORDS * 4)     // 46592

__global__ __launch_bounds__(128, 4) void attn_mma(const int* __restrict__ mask)
{
    extern __shared__ float sm[];
    uint32_t smb;
    asm("{ .reg .u64 tt; cvta.to.shared.u64 tt, %1; cvt.u32.u64 %0, tt; }"
        : "=r"(smb) : "l"(sm));

    const int tid  = threadIdx.x;
    const int warp = tid >> 5, lane = tid & 31;
    const int g = lane >> 2, t = lane & 3;
    const int wrow = warp * 16;

    const int b  = blockIdx.y;
    const int z  = blockIdx.z;
    const int q0 = blockIdx.x * 64;
    const uint16_t* qb = g_qh + ((size_t)b * SEQ + q0) * DIM;
    const uint16_t* kb = g_kh + ((size_t)b * SEQ + z * SEQH) * DIM;
    const uint16_t* vb = g_vh + ((size_t)b * SEQ + z * SEQH) * DIM;
    const int*      mb = mask + (size_t)b * SEQ + z * SEQH;

    // ---- prologue: stage Q + tile0 ----
    #pragma unroll
    for (int i = 0; i < 4; i++) {
        const int c = tid + i*128;
        const int row = c >> 3, w4 = (c & 7) << 2;
        cpa16(smb + 4u*(SM_Q + row*HST + w4), qb + (size_t)row*DIM + w4*2);
    }
    #pragma unroll
    for (int i = 0; i < 4; i++) {
        const int c = tid + i*128;
        const int key = c >> 3, w4 = (c & 7) << 2;
        cpa16(smb + 4u*(SM_K0 + key*HST + w4), kb + (size_t)key*DIM + w4*2);
    }
    #pragma unroll
    for (int i = 0; i < 4; i++) {
        const int c = tid + i*128;
        const int key = c >> 3, w4 = (c & 7) << 2;
        cpa16(smb + 4u*(SM_V0 + key*HST + w4), vb + (size_t)key*DIM + w4*2);
    }
    if (tid < 16)
        cpa16(smb + 4u*(SM_MK0 + tid*4), mb + tid*4);
    cpa_commit();
    cpa_wait0();
    __syncthreads();

    // ---- hoist Q fragments ----
    uint32_t qf[4][4];
    {
        const int mat = lane >> 3, r7 = lane & 7;
        const uint32_t qrow = smb + 4u*(SM_Q + (wrow + ((mat & 1) << 3) + r7) * HST
                                        + ((mat >> 1) << 2));
        #pragma unroll
        for (int kc = 0; kc < 4; kc++)
            ldsm_x4(qf[kc][0], qf[kc][1], qf[kc][2], qf[kc][3], qrow + 4u*(kc*8));
    }

    float o[8][4];
    #pragma unroll
    for (int nt = 0; nt < 8; nt++)
        #pragma unroll
        for (int j = 0; j < 4; j++) o[nt][j] = 0.f;
    float m0 = -1e30f, m1 = -1e30f, l0 = 0.f, l1 = 0.f;

    const int kmat = lane >> 3, kr7 = lane & 7;
    const int kkey_off = ((kmat >> 1) << 3) + kr7;
    const int kcol_off = (kmat & 1) << 2;
    const int vrow = (((lane >> 3) & 1) << 3) + (lane & 7);
    const int vcol4 = ((lane >> 3) >> 1) << 2;

    for (int kt = 0; kt < SEQH/64; kt++) {
        const int buf = kt & 1;
        cpa_wait0();
        __syncthreads();

        if (kt < SEQH/64 - 1) {
            const int kbw = buf ? SM_K0 : SM_K1;
            const int vbw = buf ? SM_V0 : SM_V1;
            const int mbw = buf ? SM_MK0 : SM_MK1;
            const size_t kofs = (size_t)(kt + 1) * 64;
            #pragma unroll
            for (int i = 0; i < 4; i++) {
                const int c = tid + i*128;
                const int key = c >> 3, w4 = (c & 7) << 2;
                cpa16(smb + 4u*(kbw + key*HST + w4), kb + (kofs + key)*DIM + w4*2);
            }
            #pragma unroll
            for (int i = 0; i < 4; i++) {
                const int c = tid + i*128;
                const int key = c >> 3, w4 = (c & 7) << 2;
                cpa16(smb + 4u*(vbw + key*HST + w4), vb + (kofs + key)*DIM + w4*2);
            }
            if (tid < 16)
                cpa16(smb + 4u*(mbw + tid*4), mb + kofs + tid*4);
            cpa_commit();
        }

        const int*     Mc  = (const int*)sm + (buf ? SM_MK1 : SM_MK0);
        const uint32_t kba = smb + 4u*((buf ? SM_K1 : SM_K0) + kkey_off*HST + kcol_off);
        const uint32_t vba = smb + 4u*((buf ? SM_V1 : SM_V0) + vrow*HST + vcol4);

        // ---- S = Q @ K^T ----
        float c[8][4];
        #pragma unroll
        for (int nt = 0; nt < 8; nt++)
            #pragma unroll
            for (int j = 0; j < 4; j++) c[nt][j] = 0.f;

        #pragma unroll
        for (int kc = 0; kc < 4; kc++) {
            #pragma unroll
            for (int np = 0; np < 4; np++) {
                uint32_t b0, b1, b2, b3;
                ldsm_x4(b0, b1, b2, b3, kba + 4u*(np*16*HST + kc*8));
                mma16(c[2*np],     qf[kc][0], qf[kc][1], qf[kc][2], qf[kc][3], b0, b1);
                mma16(c[2*np + 1], qf[kc][0], qf[kc][1], qf[kc][2], qf[kc][3], b2, b3);
            }
        }

        // ---- mask + row max ----
        float mx0 = -1e30f, mx1 = -1e30f;
        #pragma unroll
        for (int nt = 0; nt < 8; nt++) {
            int2 mv = *(const int2*)(Mc + nt*8 + 2*t);
            if (mv.x == 0) { c[nt][0] = -1e9f; c[nt][2] = -1e9f; }
            if (mv.y == 0) { c[nt][1] = -1e9f; c[nt][3] = -1e9f; }
            mx0 = fmaxf(mx0, fmaxf(c[nt][0], c[nt][1]));
            mx1 = fmaxf(mx1, fmaxf(c[nt][2], c[nt][3]));
        }
        mx0 = fmaxf(mx0, __shfl_xor_sync(0xffffffffu, mx0, 1));
        mx0 = fmaxf(mx0, __shfl_xor_sync(0xffffffffu, mx0, 2));
        mx1 = fmaxf(mx1, __shfl_xor_sync(0xffffffffu, mx1, 1));
        mx1 = fmaxf(mx1, __shfl_xor_sync(0xffffffffu, mx1, 2));

        const float mn0 = fmaxf(m0, mx0), mn1 = fmaxf(m1, mx1);

        float s0 = 0.f, s1 = 0.f;
        #pragma unroll
        for (int nt = 0; nt < 8; nt++) {
            c[nt][0] = __expf(c[nt][0] - mn0);
            c[nt][1] = __expf(c[nt][1] - mn0);
            c[nt][2] = __expf(c[nt][2] - mn1);
            c[nt][3] = __expf(c[nt][3] - mn1);
            s0 += c[nt][0] + c[nt][1];
            s1 += c[nt][2] + c[nt][3];
        }
        s0 += __shfl_xor_sync(0xffffffffu, s0, 1);
        s0 += __shfl_xor_sync(0xffffffffu, s0, 2);
        s1 += __shfl_xor_sync(0xffffffffu, s1, 1);
        s1 += __shfl_xor_sync(0xffffffffu, s1, 2);

        const float co0 = __expf(m0 - mn0), co1 = __expf(m1 - mn1);
        m0 = mn0; m1 = mn1;
        l0 = l0 * co0 + s0;
        l1 = l1 * co1 + s1;

        #pragma unroll
        for (int nt = 0; nt < 8; nt++) {
            o[nt][0] *= co0; o[nt][1] *= co0;
            o[nt][2] *= co1; o[nt][3] *= co1;
        }

        // ---- O += P @ V ----
        #pragma unroll
        for (int kc = 0; kc < 4; kc++) {
            uint32_t a0 = h2(c[2*kc][0],   c[2*kc][1]);
            uint32_t a1 = h2(c[2*kc][2],   c[2*kc][3]);
            uint32_t a2 = h2(c[2*kc+1][0], c[2*kc+1][1]);
            uint32_t a3 = h2(c[2*kc+1][2], c[2*kc+1][3]);
            #pragma unroll
            for (int ntp = 0; ntp < 4; ntp++) {
                uint32_t b0, b1, b2, b3;
                ldsm_x4_t(b0, b1, b2, b3, vba + 4u*(kc*16*HST + ntp*8));
                mma16(o[2*ntp],     a0, a1, a2, a3, b0, b1);
                mma16(o[2*ntp + 1], a0, a1, a2, a3, b2, b3);
            }
        }
    }

    // ---- epilogue: write unnormalized partial O + (m,l) ----
    const int ridx = b * SEQ + q0 + wrow + g;
    float* pob = g_po[z] + (size_t)ridx * DIM + 2*t;
    #pragma unroll
    for (int nt = 0; nt < 8; nt++) {
        *(float2*)(pob + nt*8)         = make_float2(o[nt][0], o[nt][1]);
        *(float2*)(pob + nt*8 + 8*DIM) = make_float2(o[nt][2], o[nt][3]);
    }
    if (t == 0) {
        g_pm[z][ridx]     = m0;  g_pl[z][ridx]     = l0;
        g_pm[z][ridx + 8] = m1;  g_pl[z][ridx + 8] = l1;
    }
}

// ---------------------------------------------------------------------------
// Merge 4 partials: out = sum_z o_z*c_z / sum_z l_z*c_z, c_z = exp(m_z - m)
// ---------------------------------------------------------------------------
__global__ __launch_bounds__(256) void merge_k(float* __restrict__ out)
{
    const int e = blockIdx.x * 256 + threadIdx.x;   // float4 index
    const int row = e >> 4;                         // 16 float4 per row
    float m = -1e30f;
    #pragma unroll
    for (int z = 0; z < NSPL; z++) m = fmaxf(m, g_pm[z][row]);
    float4 acc = make_float4(0.f, 0.f, 0.f, 0.f);
    float denom = 0.f;
    #pragma unroll
    for (int z = 0; z < NSPL; z++) {
        const float cz = __expf(g_pm[z][row] - m);
        denom += g_pl[z][row] * cz;
        float4 a = ((const float4*)g_po[z])[e];
        acc.x += a.x * cz; acc.y += a.y * cz;
        acc.z += a.z * cz; acc.w += a.w * cz;
    }
    const float inv = 1.f / denom;
    ((float4*)out)[e] = make_float4(acc.x*inv, acc.y*inv, acc.z*inv, acc.w*inv);
}

// ---------------------------------------------------------------------------
extern "C" void kernel_launch(void* const* d_in, const int* in_sizes, int n_in,
                              void* d_out, int out_size)
{
    const float* query = (const float*)d_in[0];
    const float* key_  = (const float*)d_in[1];
    const float* value = (const float*)d_in[2];
    const int*   mask  = (const int*)d_in[3];
    const float* Wq = (const float*)d_in[4];
    const float* bq = (const float*)d_in[5];
    const float* Wk = (const float*)d_in[6];
    const float* bk = (const float*)d_in[7];
    const float* Wv = (const float*)d_in[8];
    const float* bv = (const float*)d_in[9];
    float* out = (float*)d_out;

    cudaFuncSetAttribute(proj_mma, cudaFuncAttributeMaxDynamicSharedMemorySize,
                         PROJ_SMEM_BYTES);
    cudaFuncSetAttribute(attn_mma, cudaFuncAttributeMaxDynamicSharedMemorySize,
                         ATTN_SMEM_BYTES);

    dim3 gp(M_TOT / 128, 1, 3);
    proj_mma<<<gp, 256, PROJ_SMEM_BYTES>>>(query, key_, value,
                                           Wq, bq, Wk, bk, Wv, bv);

    dim3 ga(SEQ / 64, BATCH, NSPL);
    attn_mma<<<ga, 128, ATTN_SMEM_BYTES>>>(mask);

    merge_k<<<(M_TOT * DIM / 4) / 256, 256>>>(out);
}